// round 6
// baseline (speedup 1.0000x reference)
#include <cuda_runtime.h>
#include <cuda_bf16.h>
#include <cstdint>

// Problem constants
#define BATCH 256
#define TT    256
#define DM    384
#define DKV   64
#define BT    (BATCH*TT)

// ---------------------------------------------------------------------------
// Scratch
// ---------------------------------------------------------------------------
__device__ float g_q[BT * DKV];
__device__ float g_k[BT * DKV];
__device__ float g_v[BT * DKV];
// W^T packed [192 n][384 k], bf16 hi / lo split. n: 0-63=Wq, 64-127=Wk, 128-191=Wv
__device__ __align__(16) __nv_bfloat16 g_wth[192 * DM];
__device__ __align__(16) __nv_bfloat16 g_wtl[192 * DM];

// ---------------------------------------------------------------------------
// PTX helpers (sm_80-era: mma.sync + ldmatrix, valid at compute_103)
// ---------------------------------------------------------------------------
__device__ __forceinline__ uint32_t smem_u32(const void* p) {
    uint32_t a;
    asm("{ .reg .u64 t; cvta.to.shared.u64 t, %1; cvt.u32.u64 %0, t; }"
        : "=r"(a) : "l"(p));
    return a;
}
__device__ __forceinline__ void ldsm_x4(uint32_t addr, uint32_t* r) {
    asm volatile("ldmatrix.sync.aligned.m8n8.x4.shared.b16 {%0,%1,%2,%3}, [%4];"
                 : "=r"(r[0]), "=r"(r[1]), "=r"(r[2]), "=r"(r[3]) : "r"(addr));
}
__device__ __forceinline__ void ldsm_x4t(uint32_t addr, uint32_t* r) {
    asm volatile("ldmatrix.sync.aligned.m8n8.x4.trans.shared.b16 {%0,%1,%2,%3}, [%4];"
                 : "=r"(r[0]), "=r"(r[1]), "=r"(r[2]), "=r"(r[3]) : "r"(addr));
}
__device__ __forceinline__ void mma_bf16(float* c, const uint32_t* a,
                                         uint32_t b0, uint32_t b1) {
    asm volatile(
        "mma.sync.aligned.m16n8k16.row.col.f32.bf16.bf16.f32 "
        "{%0,%1,%2,%3}, {%4,%5,%6,%7}, {%8,%9}, {%0,%1,%2,%3};"
        : "+f"(c[0]), "+f"(c[1]), "+f"(c[2]), "+f"(c[3])
        : "r"(a[0]), "r"(a[1]), "r"(a[2]), "r"(a[3]), "r"(b0), "r"(b1));
}
__device__ __forceinline__ float ex2(float x) {
    float y;
    asm("ex2.approx.ftz.f32 %0, %1;" : "=f"(y) : "f"(x));
    return y;
}
// split float2 into packed bf16x2 hi and lo
__device__ __forceinline__ void split2(float x, float y, uint32_t& h, uint32_t& l) {
    __nv_bfloat16 h0 = __float2bfloat16(x), h1 = __float2bfloat16(y);
    __nv_bfloat16 l0 = __float2bfloat16(x - __bfloat162float(h0));
    __nv_bfloat16 l1 = __float2bfloat16(y - __bfloat162float(h1));
    __nv_bfloat162 hp = __halves2bfloat162(h0, h1);
    __nv_bfloat162 lp = __halves2bfloat162(l0, l1);
    h = *(uint32_t*)&hp; l = *(uint32_t*)&lp;
}

// ---------------------------------------------------------------------------
// Kernel 0: W^T hi/lo bf16 conversion
// ---------------------------------------------------------------------------
__global__ void wconv_kernel(const float* __restrict__ Wq,
                             const float* __restrict__ Wk,
                             const float* __restrict__ Wv) {
    int idx = blockIdx.x * 256 + threadIdx.x;
    if (idx >= 192 * DM) return;
    int n = idx / DM, k = idx % DM;
    const float* W = (n < 64) ? Wq : (n < 128) ? Wk : Wv;
    float x = W[k * DKV + (n & 63)];
    __nv_bfloat16 h = __float2bfloat16(x);
    g_wth[idx] = h;
    g_wtl[idx] = __float2bfloat16(x - __bfloat162float(h));
}

// ---------------------------------------------------------------------------
// Kernel 1: fused QKV projection via mma.sync bf16 (hi/lo 3-pass).
//   BM=64 x BN=192 per CTA (grid 1024), 2 CTAs/SM resident: cross-CTA
//   overlap hides the k-step store/sync tail and LDG latency.
//   Warp tile 16x96 (acc 48 regs). K loop 12 x 32, smem double-buffered.
// ---------------------------------------------------------------------------
#define BM   64
#define BN   192
#define BKS  32
#define NKS  (DM / BKS)
#define PAD  40

#define A_SZ (BM * PAD)          // 2560
#define B_SZ (BN * PAD)          // 7680
#define OFF_AH(buf) ((buf) * A_SZ)
#define OFF_AL(buf) (2 * A_SZ + (buf) * A_SZ)
#define OFF_BH(buf) (4 * A_SZ + (buf) * B_SZ)
#define OFF_BL(buf) (4 * A_SZ + 2 * B_SZ + (buf) * B_SZ)
#define SM_ELEMS    (4 * A_SZ + 4 * B_SZ)            // 40960 bf16 = 80 KB

__global__ void __launch_bounds__(256, 2) proj_mma_kernel(const float* __restrict__ X) {
    extern __shared__ __nv_bfloat16 sm[];
    const uint32_t sb = smem_u32(sm);

    const int tid    = threadIdx.x;
    const int lane   = tid & 31;
    const int wid    = tid >> 5;
    const int warp_m = wid & 3;          // 4 warps along M: 16 rows each
    const int warp_n = wid >> 2;         // 2 warps along N: 96 cols each
    const int row0   = blockIdx.x * BM;

    float acc[12][4];
    #pragma unroll
    for (int n = 0; n < 12; n++)
        #pragma unroll
        for (int j = 0; j < 4; j++) acc[n][j] = 0.f;

    // staging registers
    float4 xa[2];
    uint4  bhs[3], bls[3];

    auto load_regs = [&](int ks) {
        const int k0 = ks * BKS;
        #pragma unroll
        for (int i = 0; i < 2; i++) {
            int f  = tid + i * 256;          // 0..511
            int r  = f >> 3;                 // 0..63
            int c4 = f & 7;
            xa[i] = *(const float4*)(X + (size_t)(row0 + r) * DM + k0 + c4 * 4);
        }
        #pragma unroll
        for (int i = 0; i < 3; i++) {
            int f  = tid + i * 256;          // 0..767
            int r  = f >> 2;                 // 0..191
            int c8 = f & 3;
            int e  = r * DM + k0 + c8 * 8;
            bhs[i] = *(const uint4*)(g_wth + e);
            bls[i] = *(const uint4*)(g_wtl + e);
        }
    };

    auto store_tile = [&](int buf) {
        #pragma unroll
        for (int i = 0; i < 2; i++) {
            int f  = tid + i * 256;
            int r  = f >> 3;
            int c4 = f & 7;
            float4 v = xa[i];
            uint32_t h0, l0, h1, l1;
            split2(v.x, v.y, h0, l0);
            split2(v.z, v.w, h1, l1);
            int e = r * PAD + c4 * 4;
            *(uint2*)(sm + OFF_AH(buf) + e) = make_uint2(h0, h1);
            *(uint2*)(sm + OFF_AL(buf) + e) = make_uint2(l0, l1);
        }
        #pragma unroll
        for (int i = 0; i < 3; i++) {
            int f  = tid + i * 256;
            int r  = f >> 2;
            int c8 = f & 3;
            int e  = r * PAD + c8 * 8;
            *(uint4*)(sm + OFF_BH(buf) + e) = bhs[i];
            *(uint4*)(sm + OFF_BL(buf) + e) = bls[i];
        }
    };

    load_regs(0);
    store_tile(0);
    __syncthreads();

    for (int ks = 0; ks < NKS; ks++) {
        const int cur = ks & 1;
        if (ks + 1 < NKS) load_regs(ks + 1);

        const uint32_t ah_base = sb + OFF_AH(cur) * 2;
        const uint32_t al_base = sb + OFF_AL(cur) * 2;
        const uint32_t bh_base = sb + OFF_BH(cur) * 2;
        const uint32_t bl_base = sb + OFF_BL(cur) * 2;

        #pragma unroll
        for (int kk = 0; kk < 2; kk++) {
            uint32_t ah[4], al[4];
            const int arow = warp_m * 16 + (lane & 15);
            const int acol = kk * 16 + ((lane >> 4) << 3);
            const uint32_t aoff = (uint32_t)(arow * PAD + acol) * 2;
            ldsm_x4(ah_base + aoff, ah);
            ldsm_x4(al_base + aoff, al);

            const int brow_l = (lane & 7) + ((lane & 16) >> 1);
            const int bcol   = kk * 16 + (lane & 8);
            #pragma unroll
            for (int g = 0; g < 6; g++) {
                uint32_t bh[4], bl[4];
                const int brow = warp_n * 96 + g * 16 + brow_l;
                const uint32_t boff = (uint32_t)(brow * PAD + bcol) * 2;
                ldsm_x4(bh_base + boff, bh);
                ldsm_x4(bl_base + boff, bl);
                #pragma unroll
                for (int h = 0; h < 2; h++) {
                    float* c = acc[g * 2 + h];
                    mma_bf16(c, ah, bh[h * 2], bh[h * 2 + 1]);
                    mma_bf16(c, ah, bl[h * 2], bl[h * 2 + 1]);
                    mma_bf16(c, al, bh[h * 2], bh[h * 2 + 1]);
                }
            }
        }

        if (ks + 1 < NKS) {
            __syncthreads();
            store_tile(cur ^ 1);
            __syncthreads();
        }
    }

    const int gi = lane >> 2;
    const int ti = lane & 3;
    {
        const int row = row0 + warp_m * 16 + gi;
        #pragma unroll
        for (int nt = 0; nt < 12; nt++) {
            const int col  = warp_n * 96 + nt * 8 + ti * 2;
            float* dstbase = (col < 64) ? g_q : (col < 128) ? g_k : g_v;
            float* d0 = dstbase + (size_t)row * DKV + (col & 63);
            float* d1 = dstbase + (size_t)(row + 8) * DKV + (col & 63);
            *(float2*)d0 = make_float2(acc[nt][0], acc[nt][1]);
            *(float2*)d1 = make_float2(acc[nt][2], acc[nt][3]);
        }
    }
}

// ---------------------------------------------------------------------------
// Kernel 2: causal attention on mma.sync (flash-style, hi/lo everywhere).
//   CTA = 1 batch. K,V hi/lo bf16 in smem (PAD 72 -> 144B stride, conflict-
//   free ldmatrix). Each warp: 32 queries (2 m16 tiles), loops its key
//   blocks of 16 independently (no syncs). Q frags from gmem; P frags
//   derived in-register from S accumulators. exp2-domain online softmax.
// ---------------------------------------------------------------------------
#define APAD 72
#define KV_SZ (TT * APAD)       // 18432 elems per buffer

__global__ void __launch_bounds__(256, 1) attn_mma_kernel(float* __restrict__ out) {
    extern __shared__ __nv_bfloat16 smk[];
    __nv_bfloat16* Kh = smk;
    __nv_bfloat16* Kl = smk + KV_SZ;
    __nv_bfloat16* Vh = smk + 2 * KV_SZ;
    __nv_bfloat16* Vl = smk + 3 * KV_SZ;

    const int b    = blockIdx.x;
    const int tid  = threadIdx.x;
    const int lane = tid & 31;
    const int wid  = tid >> 5;

    // ---- prologue: K,V fp32 -> smem bf16 hi/lo ----
    {
        const float4* Kg = (const float4*)(g_k + (size_t)b * TT * DKV);
        const float4* Vg = (const float4*)(g_v + (size_t)b * TT * DKV);
        #pragma unroll
        for (int i0 = 0; i0 < 16; i0++) {
            int i = tid + i0 * 256;           // 0..4095
            int r = i >> 4, c4 = (i & 15) * 4;
            int e = r * APAD + c4;
            float4 kv = Kg[i];
            uint32_t h0, l0, h1, l1;
            split2(kv.x, kv.y, h0, l0);
            split2(kv.z, kv.w, h1, l1);
            *(uint2*)(Kh + e) = make_uint2(h0, h1);
            *(uint2*)(Kl + e) = make_uint2(l0, l1);
            float4 vv = Vg[i];
            split2(vv.x, vv.y, h0, l0);
            split2(vv.z, vv.w, h1, l1);
            *(uint2*)(Vh + e) = make_uint2(h0, h1);
            *(uint2*)(Vl + e) = make_uint2(l0, l1);
        }
    }

    // ---- Q fragments (gmem -> regs), scaled by 0.125*log2(e) ----
    const int qb = (wid < 4) ? wid : (11 - wid);   // SMSP balance: pairs sum 288
    const int Q0 = qb * 32;
    const int g  = lane >> 2;
    const int tg = lane & 3;
    const float SC = 0.125f * 1.44269504f;

    uint32_t qh[2][4][4], ql[2][4][4];
    {
        const float* Qb = g_q + ((size_t)b * TT + Q0) * DKV;
        #pragma unroll
        for (int mt = 0; mt < 2; mt++) {
            #pragma unroll
            for (int kk = 0; kk < 4; kk++) {
                const int r0 = mt * 16 + g;
                const int c0 = kk * 16 + tg * 2;
                float2 v00 = *(const float2*)(Qb + r0 * DKV + c0);
                float2 v01 = *(const float2*)(Qb + r0 * DKV + c0 + 8);
                float2 v10 = *(const float2*)(Qb + (r0 + 8) * DKV + c0);
                float2 v11 = *(const float2*)(Qb + (r0 + 8) * DKV + c0 + 8);
                split2(v00.x * SC, v00.y * SC, qh[mt][kk][0], ql[mt][kk][0]);
                split2(v10.x * SC, v10.y * SC, qh[mt][kk][1], ql[mt][kk][1]);
                split2(v01.x * SC, v01.y * SC, qh[mt][kk][2], ql[mt][kk][2]);
                split2(v11.x * SC, v11.y * SC, qh[mt][kk][3], ql[mt][kk][3]);
            }
        }
    }
    __syncthreads();

    const uint32_t sbKh = smem_u32(Kh), sbKl = smem_u32(Kl);
    const uint32_t sbVh = smem_u32(Vh), sbVl = smem_u32(Vl);

    float m[4] = {-1e30f, -1e30f, -1e30f, -1e30f};
    float lsum[4] = {0.f, 0.f, 0.f, 0.f};
    float O[2][8][4];
    #pragma unroll
    for (int mt = 0; mt < 2; mt++)
        #pragma unroll
        for (int n = 0; n < 8; n++)
            #pragma unroll
            for (int j = 0; j < 4; j++) O[mt][n][j] = 0.f;

    const int krow = (lane & 7) + ((lane & 16) >> 1);   // K/B frag row
    const int koff = (lane & 8);                        // k-offset within k16
    const int vkey = lane & 15;                         // V/B trans frag row
    const int voff = (lane >> 4) << 3;                  // n-offset

    const int nblk = qb * 2 + 2;
    for (int kb = 0; kb < nblk; kb++) {
        const int j0 = kb * 16;
        const bool msk = (kb >= qb * 2);

        // ---- S = Q K^T (hi/lo 3-pass) ----
        float S[2][2][4];
        #pragma unroll
        for (int mt = 0; mt < 2; mt++)
            #pragma unroll
            for (int nt = 0; nt < 2; nt++)
                #pragma unroll
                for (int j = 0; j < 4; j++) S[mt][nt][j] = 0.f;

        const uint32_t kb_h = sbKh + (uint32_t)((j0 + krow) * APAD + koff) * 2;
        const uint32_t kb_l = sbKl + (uint32_t)((j0 + krow) * APAD + koff) * 2;
        #pragma unroll
        for (int kk = 0; kk < 4; kk++) {
            uint32_t bh[4], bl[4];
            ldsm_x4(kb_h + kk * 32, bh);
            ldsm_x4(kb_l + kk * 32, bl);
            #pragma unroll
            for (int mt = 0; mt < 2; mt++) {
                mma_bf16(S[mt][0], qh[mt][kk], bh[0], bh[1]);
                mma_bf16(S[mt][1], qh[mt][kk], bh[2], bh[3]);
                mma_bf16(S[mt][0], qh[mt][kk], bl[0], bl[1]);
                mma_bf16(S[mt][1], qh[mt][kk], bl[2], bl[3]);
                mma_bf16(S[mt][0], ql[mt][kk], bh[0], bh[1]);
                mma_bf16(S[mt][1], ql[mt][kk], bh[2], bh[3]);
            }
        }

        // ---- causal mask ----
        if (msk) {
            #pragma unroll
            for (int mt = 0; mt < 2; mt++)
                #pragma unroll
                for (int nt = 0; nt < 2; nt++)
                    #pragma unroll
                    for (int j = 0; j < 4; j++) {
                        const int row = Q0 + mt * 16 + g + ((j >> 1) << 3);
                        const int col = j0 + nt * 8 + tg * 2 + (j & 1);
                        if (col > row) S[mt][nt][j] = -1e30f;
                    }
        }

        // ---- online softmax + P frag build ----
        uint32_t pah[2][4], pal[2][4];
        #pragma unroll
        for (int mt = 0; mt < 2; mt++) {
            #pragma unroll
            for (int h = 0; h < 2; h++) {
                const int rg = mt * 2 + h;
                float v0 = S[mt][0][h * 2], v1 = S[mt][0][h * 2 + 1];
                float v2 = S[mt][1][h * 2], v3 = S[mt][1][h * 2 + 1];
                float mx = fmaxf(fmaxf(v0, v1), fmaxf(v2, v3));
                mx = fmaxf(mx, __shfl_xor_sync(0xFFFFFFFFu, mx, 1));
                mx = fmaxf(mx, __shfl_xor_sync(0xFFFFFFFFu, mx, 2));
                const float mnew = fmaxf(m[rg], mx);
                const float sc   = ex2(m[rg] - mnew);
                m[rg] = mnew;
                const float p0 = ex2(v0 - mnew), p1 = ex2(v1 - mnew);
                const float p2 = ex2(v2 - mnew), p3 = ex2(v3 - mnew);
                lsum[rg] = lsum[rg] * sc + (p0 + p1 + p2 + p3);
                #pragma unroll
                for (int n = 0; n < 8; n++) {
                    O[mt][n][h * 2]     *= sc;
                    O[mt][n][h * 2 + 1] *= sc;
                }
                split2(p0, p1, pah[mt][h],     pal[mt][h]);
                split2(p2, p3, pah[mt][2 + h], pal[mt][2 + h]);
            }
        }

        // ---- O += P V (hi/lo 3-pass) ----
        const uint32_t vb_h = sbVh + (uint32_t)((j0 + vkey) * APAD + voff) * 2;
        const uint32_t vb_l = sbVl + (uint32_t)((j0 + vkey) * APAD + voff) * 2;
        #pragma unroll
        for (int nc = 0; nc < 4; nc++) {
            uint32_t vh4[4], vl4[4];
            ldsm_x4t(vb_h + nc * 32, vh4);
            ldsm_x4t(vb_l + nc * 32, vl4);
            #pragma unroll
            for (int mt = 0; mt < 2; mt++) {
                mma_bf16(O[mt][nc * 2],     pah[mt], vh4[0], vh4[1]);
                mma_bf16(O[mt][nc * 2 + 1], pah[mt], vh4[2], vh4[3]);
                mma_bf16(O[mt][nc * 2],     pal[mt], vh4[0], vh4[1]);
                mma_bf16(O[mt][nc * 2 + 1], pal[mt], vh4[2], vh4[3]);
                mma_bf16(O[mt][nc * 2],     pah[mt], vl4[0], vl4[1]);
                mma_bf16(O[mt][nc * 2 + 1], pah[mt], vl4[2], vl4[3]);
            }
        }
    }

    // ---- epilogue: quad-reduce l, normalize, store ----
    float inv[4];
    #pragma unroll
    for (int rg = 0; rg < 4; rg++) {
        float ls = lsum[rg];
        ls += __shfl_xor_sync(0xFFFFFFFFu, ls, 1);
        ls += __shfl_xor_sync(0xFFFFFFFFu, ls, 2);
        inv[rg] = 1.f / ls;
    }
    float* ob = out + ((size_t)b * TT) * DKV;
    #pragma unroll
    for (int mt = 0; mt < 2; mt++) {
        #pragma unroll
        for (int h = 0; h < 2; h++) {
            const int row = Q0 + mt * 16 + g + h * 8;
            const float iv = inv[mt * 2 + h];
            #pragma unroll
            for (int n = 0; n < 8; n++) {
                *(float2*)(ob + (size_t)row * DKV + n * 8 + tg * 2) =
                    make_float2(O[mt][n][h * 2] * iv, O[mt][n][h * 2 + 1] * iv);
            }
        }
    }
}

// ---------------------------------------------------------------------------
// kernel_launch — graph-capturable, allocation-free
// ---------------------------------------------------------------------------
extern "C" void kernel_launch(void* const* d_in, const int* in_sizes, int n_in,
                              void* d_out, int out_size) {
    const float* x  = (const float*)d_in[0];
    const float* Wq = (const float*)d_in[1];
    const float* Wk = (const float*)d_in[2];
    const float* Wv = (const float*)d_in[3];
    float* out = (float*)d_out;
    (void)in_sizes; (void)n_in; (void)out_size;

    wconv_kernel<<<(192 * DM + 255) / 256, 256>>>(Wq, Wk, Wv);

    const int proj_smem = SM_ELEMS * (int)sizeof(__nv_bfloat16);   // 80 KB
    cudaFuncSetAttribute(proj_mma_kernel,
                         cudaFuncAttributeMaxDynamicSharedMemorySize, proj_smem);
    proj_mma_kernel<<<BT / BM, 256, proj_smem>>>(x);

    const int attn_smem = 4 * KV_SZ * (int)sizeof(__nv_bfloat16);  // 144 KB
    cudaFuncSetAttribute(attn_mma_kernel,
                         cudaFuncAttributeMaxDynamicSharedMemorySize, attn_smem);
    attn_mma_kernel<<<BATCH, 256, attn_smem>>>(out);
}

// round 7
// speedup vs baseline: 1.4454x; 1.4454x over previous
#include <cuda_runtime.h>
#include <cuda_fp16.h>
#include <cstdint>

// Problem constants
#define BATCH 256
#define TT    256
#define DM    384
#define DKV   64
#define BT    (BATCH*TT)

// ---------------------------------------------------------------------------
// Scratch
// ---------------------------------------------------------------------------
__device__ float g_q[BT * DKV];
__device__ float g_k[BT * DKV];
__device__ float g_v[BT * DKV];
// W^T packed [192 n][384 k], fp16 (single pass; W rounding error ~2^-11).
__device__ __align__(16) __half g_wh[192 * DM];

// ---------------------------------------------------------------------------
// PTX helpers (sm_80-era: mma.sync + ldmatrix, valid at compute_103)
// ---------------------------------------------------------------------------
__device__ __forceinline__ uint32_t smem_u32(const void* p) {
    uint32_t a;
    asm("{ .reg .u64 t; cvta.to.shared.u64 t, %1; cvt.u32.u64 %0, t; }"
        : "=r"(a) : "l"(p));
    return a;
}
__device__ __forceinline__ void ldsm_x4(uint32_t addr, uint32_t* r) {
    asm volatile("ldmatrix.sync.aligned.m8n8.x4.shared.b16 {%0,%1,%2,%3}, [%4];"
                 : "=r"(r[0]), "=r"(r[1]), "=r"(r[2]), "=r"(r[3]) : "r"(addr));
}
__device__ __forceinline__ void ldsm_x4t(uint32_t addr, uint32_t* r) {
    asm volatile("ldmatrix.sync.aligned.m8n8.x4.trans.shared.b16 {%0,%1,%2,%3}, [%4];"
                 : "=r"(r[0]), "=r"(r[1]), "=r"(r[2]), "=r"(r[3]) : "r"(addr));
}
__device__ __forceinline__ void mma_fp16(float* c, const uint32_t* a,
                                         uint32_t b0, uint32_t b1) {
    asm volatile(
        "mma.sync.aligned.m16n8k16.row.col.f32.f16.f16.f32 "
        "{%0,%1,%2,%3}, {%4,%5,%6,%7}, {%8,%9}, {%0,%1,%2,%3};"
        : "+f"(c[0]), "+f"(c[1]), "+f"(c[2]), "+f"(c[3])
        : "r"(a[0]), "r"(a[1]), "r"(a[2]), "r"(a[3]), "r"(b0), "r"(b1));
}
__device__ __forceinline__ float ex2(float x) {
    float y;
    asm("ex2.approx.ftz.f32 %0, %1;" : "=f"(y) : "f"(x));
    return y;
}
// split float2 into packed fp16x2 hi and lo (x = h + l to ~2^-22)
__device__ __forceinline__ void split2h(float x, float y, uint32_t& h, uint32_t& l) {
    __half h0 = __float2half_rn(x), h1 = __float2half_rn(y);
    __half l0 = __float2half_rn(x - __half2float(h0));
    __half l1 = __float2half_rn(y - __half2float(h1));
    __half2 hp = __halves2half2(h0, h1);
    __half2 lp = __halves2half2(l0, l1);
    h = *(uint32_t*)&hp; l = *(uint32_t*)&lp;
}
__device__ __forceinline__ uint32_t pack2h(float x, float y) {
    __half2 hp = __halves2half2(__float2half_rn(x), __float2half_rn(y));
    return *(uint32_t*)&hp;
}

// ---------------------------------------------------------------------------
// Kernel 0: W^T fp16 conversion
// ---------------------------------------------------------------------------
__global__ void wconv_kernel(const float* __restrict__ Wq,
                             const float* __restrict__ Wk,
                             const float* __restrict__ Wv) {
    int idx = blockIdx.x * 256 + threadIdx.x;
    if (idx >= 192 * DM) return;
    int n = idx / DM, k = idx % DM;
    const float* W = (n < 64) ? Wq : (n < 128) ? Wk : Wv;
    g_wh[idx] = __float2half_rn(W[k * DKV + (n & 63)]);
}

// ---------------------------------------------------------------------------
// Kernel 1: fused QKV projection via mma.sync fp16, 2-pass (Xh*Wh + Xl*Wh).
//   BM=128 x BN=192 per CTA (R5 shape), K loop 12 x 32, smem double-buffered.
// ---------------------------------------------------------------------------
#define BM   128
#define BN   192
#define BKS  32
#define NKS  (DM / BKS)
#define PAD  40

#define A_SZ (BM * PAD)          // 5120
#define B_SZ (BN * PAD)          // 7680
#define OFF_AH(buf) ((buf) * A_SZ)
#define OFF_AL(buf) (2 * A_SZ + (buf) * A_SZ)
#define OFF_BH(buf) (4 * A_SZ + (buf) * B_SZ)
#define SM_ELEMS    (4 * A_SZ + 2 * B_SZ)            // 35840 fp16 = 70 KB

__global__ void __launch_bounds__(256, 1) proj_mma_kernel(const float* __restrict__ X) {
    extern __shared__ __half sm[];
    const uint32_t sb = smem_u32(sm);

    const int tid    = threadIdx.x;
    const int lane   = tid & 31;
    const int wid    = tid >> 5;
    const int warp_m = wid & 3;          // 4 warps along M: 32 rows each
    const int warp_n = wid >> 2;         // 2 warps along N: 96 cols each
    const int row0   = blockIdx.x * BM;

    float acc[2][12][4];
    #pragma unroll
    for (int m = 0; m < 2; m++)
        #pragma unroll
        for (int n = 0; n < 12; n++)
            #pragma unroll
            for (int j = 0; j < 4; j++) acc[m][n][j] = 0.f;

    float4 xa[4];
    uint4  bhs[3];

    auto load_regs = [&](int ks) {
        const int k0 = ks * BKS;
        #pragma unroll
        for (int i = 0; i < 4; i++) {
            int f  = tid + i * 256;          // 0..1023
            int r  = f >> 3;                 // 0..127
            int c4 = f & 7;
            xa[i] = *(const float4*)(X + (size_t)(row0 + r) * DM + k0 + c4 * 4);
        }
        #pragma unroll
        for (int i = 0; i < 3; i++) {
            int f  = tid + i * 256;          // 0..767
            int r  = f >> 2;                 // 0..191
            int c8 = f & 3;
            bhs[i] = *(const uint4*)(g_wh + r * DM + k0 + c8 * 8);
        }
    };

    auto store_tile = [&](int buf) {
        #pragma unroll
        for (int i = 0; i < 4; i++) {
            int f  = tid + i * 256;
            int r  = f >> 3;
            int c4 = f & 7;
            float4 v = xa[i];
            uint32_t h0, l0, h1, l1;
            split2h(v.x, v.y, h0, l0);
            split2h(v.z, v.w, h1, l1);
            int e = r * PAD + c4 * 4;
            *(uint2*)(sm + OFF_AH(buf) + e) = make_uint2(h0, h1);
            *(uint2*)(sm + OFF_AL(buf) + e) = make_uint2(l0, l1);
        }
        #pragma unroll
        for (int i = 0; i < 3; i++) {
            int f  = tid + i * 256;
            int r  = f >> 2;
            int c8 = f & 3;
            *(uint4*)(sm + OFF_BH(buf) + r * PAD + c8 * 8) = bhs[i];
        }
    };

    load_regs(0);
    store_tile(0);
    __syncthreads();

    for (int ks = 0; ks < NKS; ks++) {
        const int cur = ks & 1;
        if (ks + 1 < NKS) load_regs(ks + 1);

        const uint32_t ah_base = sb + OFF_AH(cur) * 2;
        const uint32_t al_base = sb + OFF_AL(cur) * 2;
        const uint32_t bh_base = sb + OFF_BH(cur) * 2;

        #pragma unroll
        for (int kk = 0; kk < 2; kk++) {
            uint32_t ah[2][4], al[2][4];
            const int arow_l = (lane & 15);
            const int acol   = kk * 16 + ((lane >> 4) << 3);
            #pragma unroll
            for (int mt = 0; mt < 2; mt++) {
                const int arow = warp_m * 32 + mt * 16 + arow_l;
                const uint32_t aoff = (uint32_t)(arow * PAD + acol) * 2;
                ldsm_x4(ah_base + aoff, ah[mt]);
                ldsm_x4(al_base + aoff, al[mt]);
            }
            const int brow_l = (lane & 7) + ((lane & 16) >> 1);
            const int bcol   = kk * 16 + (lane & 8);
            #pragma unroll
            for (int g = 0; g < 6; g++) {
                uint32_t bh[4];
                const int brow = warp_n * 96 + g * 16 + brow_l;
                ldsm_x4(bh_base + (uint32_t)(brow * PAD + bcol) * 2, bh);
                #pragma unroll
                for (int mt = 0; mt < 2; mt++) {
                    #pragma unroll
                    for (int h = 0; h < 2; h++) {
                        float* c = acc[mt][g * 2 + h];
                        mma_fp16(c, ah[mt], bh[h * 2], bh[h * 2 + 1]);
                        mma_fp16(c, al[mt], bh[h * 2], bh[h * 2 + 1]);
                    }
                }
            }
        }

        if (ks + 1 < NKS) {
            __syncthreads();
            store_tile(cur ^ 1);
            __syncthreads();
        }
    }

    const int gi = lane >> 2;
    const int ti = lane & 3;
    #pragma unroll
    for (int mt = 0; mt < 2; mt++) {
        const int row = row0 + warp_m * 32 + mt * 16 + gi;
        #pragma unroll
        for (int nt = 0; nt < 12; nt++) {
            const int col  = warp_n * 96 + nt * 8 + ti * 2;
            float* dstbase = (col < 64) ? g_q : (col < 128) ? g_k : g_v;
            float* d0 = dstbase + (size_t)row * DKV + (col & 63);
            float* d1 = dstbase + (size_t)(row + 8) * DKV + (col & 63);
            *(float2*)d0 = make_float2(acc[mt][nt][0], acc[mt][nt][1]);
            *(float2*)d1 = make_float2(acc[mt][nt][2], acc[mt][nt][3]);
        }
    }
}

// ---------------------------------------------------------------------------
// Kernel 2: causal attention on mma.sync fp16, 2-pass.
//   K,V single-pass fp16 in smem; Q and P hi/lo in registers.
//   CTA = 1 batch, warp = 32 queries, no syncs in the key loop.
// ---------------------------------------------------------------------------
#define APAD 72
#define KV_SZ (TT * APAD)       // 18432 elems per buffer

__global__ void __launch_bounds__(256, 1) attn_mma_kernel(float* __restrict__ out) {
    extern __shared__ __half smk[];
    __half* Kh = smk;
    __half* Vh = smk + KV_SZ;

    const int b    = blockIdx.x;
    const int tid  = threadIdx.x;
    const int lane = tid & 31;
    const int wid  = tid >> 5;

    // ---- prologue: K,V fp32 -> smem fp16 ----
    {
        const float4* Kg = (const float4*)(g_k + (size_t)b * TT * DKV);
        const float4* Vg = (const float4*)(g_v + (size_t)b * TT * DKV);
        #pragma unroll
        for (int i0 = 0; i0 < 16; i0++) {
            int i = tid + i0 * 256;           // 0..4095
            int r = i >> 4, c4 = (i & 15) * 4;
            int e = r * APAD + c4;
            float4 kv = Kg[i];
            *(uint2*)(Kh + e) = make_uint2(pack2h(kv.x, kv.y), pack2h(kv.z, kv.w));
            float4 vv = Vg[i];
            *(uint2*)(Vh + e) = make_uint2(pack2h(vv.x, vv.y), pack2h(vv.z, vv.w));
        }
    }

    // ---- Q fragments (gmem -> regs, hi/lo), scaled by 0.125*log2(e) ----
    const int qb = (wid < 4) ? wid : (11 - wid);   // SMSP balance: pairs sum 288
    const int Q0 = qb * 32;
    const int g  = lane >> 2;
    const int tg = lane & 3;
    const float SC = 0.125f * 1.44269504f;

    uint32_t qh[2][4][4], ql[2][4][4];
    {
        const float* Qb = g_q + ((size_t)b * TT + Q0) * DKV;
        #pragma unroll
        for (int mt = 0; mt < 2; mt++) {
            #pragma unroll
            for (int kk = 0; kk < 4; kk++) {
                const int r0 = mt * 16 + g;
                const int c0 = kk * 16 + tg * 2;
                float2 v00 = *(const float2*)(Qb + r0 * DKV + c0);
                float2 v01 = *(const float2*)(Qb + r0 * DKV + c0 + 8);
                float2 v10 = *(const float2*)(Qb + (r0 + 8) * DKV + c0);
                float2 v11 = *(const float2*)(Qb + (r0 + 8) * DKV + c0 + 8);
                split2h(v00.x * SC, v00.y * SC, qh[mt][kk][0], ql[mt][kk][0]);
                split2h(v10.x * SC, v10.y * SC, qh[mt][kk][1], ql[mt][kk][1]);
                split2h(v01.x * SC, v01.y * SC, qh[mt][kk][2], ql[mt][kk][2]);
                split2h(v11.x * SC, v11.y * SC, qh[mt][kk][3], ql[mt][kk][3]);
            }
        }
    }
    __syncthreads();

    const uint32_t sbKh = smem_u32(Kh);
    const uint32_t sbVh = smem_u32(Vh);

    float m[4] = {-1e30f, -1e30f, -1e30f, -1e30f};
    float lsum[4] = {0.f, 0.f, 0.f, 0.f};
    float O[2][8][4];
    #pragma unroll
    for (int mt = 0; mt < 2; mt++)
        #pragma unroll
        for (int n = 0; n < 8; n++)
            #pragma unroll
            for (int j = 0; j < 4; j++) O[mt][n][j] = 0.f;

    const int krow = (lane & 7) + ((lane & 16) >> 1);   // K/B frag row
    const int koff = (lane & 8);                        // k-offset within k16
    const int vkey = lane & 15;                         // V/B trans frag row
    const int voff = (lane >> 4) << 3;                  // n-offset

    const int nblk = qb * 2 + 2;
    for (int kb = 0; kb < nblk; kb++) {
        const int j0 = kb * 16;
        const bool msk = (kb >= qb * 2);

        // ---- S = Q K^T (Q hi/lo, K single) ----
        float S[2][2][4];
        #pragma unroll
        for (int mt = 0; mt < 2; mt++)
            #pragma unroll
            for (int nt = 0; nt < 2; nt++)
                #pragma unroll
                for (int j = 0; j < 4; j++) S[mt][nt][j] = 0.f;

        const uint32_t kb_h = sbKh + (uint32_t)((j0 + krow) * APAD + koff) * 2;
        #pragma unroll
        for (int kk = 0; kk < 4; kk++) {
            uint32_t bh[4];
            ldsm_x4(kb_h + kk * 32, bh);
            #pragma unroll
            for (int mt = 0; mt < 2; mt++) {
                mma_fp16(S[mt][0], qh[mt][kk], bh[0], bh[1]);
                mma_fp16(S[mt][1], qh[mt][kk], bh[2], bh[3]);
                mma_fp16(S[mt][0], ql[mt][kk], bh[0], bh[1]);
                mma_fp16(S[mt][1], ql[mt][kk], bh[2], bh[3]);
            }
        }

        // ---- causal mask ----
        if (msk) {
            #pragma unroll
            for (int mt = 0; mt < 2; mt++)
                #pragma unroll
                for (int nt = 0; nt < 2; nt++)
                    #pragma unroll
                    for (int j = 0; j < 4; j++) {
                        const int row = Q0 + mt * 16 + g + ((j >> 1) << 3);
                        const int col = j0 + nt * 8 + tg * 2 + (j & 1);
                        if (col > row) S[mt][nt][j] = -1e30f;
                    }
        }

        // ---- online softmax + P frag build (hi/lo) ----
        uint32_t pah[2][4], pal[2][4];
        #pragma unroll
        for (int mt = 0; mt < 2; mt++) {
            #pragma unroll
            for (int h = 0; h < 2; h++) {
                const int rg = mt * 2 + h;
                float v0 = S[mt][0][h * 2], v1 = S[mt][0][h * 2 + 1];
                float v2 = S[mt][1][h * 2], v3 = S[mt][1][h * 2 + 1];
                float mx = fmaxf(fmaxf(v0, v1), fmaxf(v2, v3));
                mx = fmaxf(mx, __shfl_xor_sync(0xFFFFFFFFu, mx, 1));
                mx = fmaxf(mx, __shfl_xor_sync(0xFFFFFFFFu, mx, 2));
                const float mnew = fmaxf(m[rg], mx);
                const float sc   = ex2(m[rg] - mnew);
                m[rg] = mnew;
                const float p0 = ex2(v0 - mnew), p1 = ex2(v1 - mnew);
                const float p2 = ex2(v2 - mnew), p3 = ex2(v3 - mnew);
                lsum[rg] = lsum[rg] * sc + (p0 + p1 + p2 + p3);
                #pragma unroll
                for (int n = 0; n < 8; n++) {
                    O[mt][n][h * 2]     *= sc;
                    O[mt][n][h * 2 + 1] *= sc;
                }
                split2h(p0, p1, pah[mt][h],     pal[mt][h]);
                split2h(p2, p3, pah[mt][2 + h], pal[mt][2 + h]);
            }
        }

        // ---- O += P V (P hi/lo, V single) ----
        const uint32_t vb_h = sbVh + (uint32_t)((j0 + vkey) * APAD + voff) * 2;
        #pragma unroll
        for (int nc = 0; nc < 4; nc++) {
            uint32_t vh4[4];
            ldsm_x4t(vb_h + nc * 32, vh4);
            #pragma unroll
            for (int mt = 0; mt < 2; mt++) {
                mma_fp16(O[mt][nc * 2],     pah[mt], vh4[0], vh4[1]);
                mma_fp16(O[mt][nc * 2 + 1], pah[mt], vh4[2], vh4[3]);
                mma_fp16(O[mt][nc * 2],     pal[mt], vh4[0], vh4[1]);
                mma_fp16(O[mt][nc * 2 + 1], pal[mt], vh4[2], vh4[3]);
            }
        }
    }

    // ---- epilogue: quad-reduce l, normalize, store ----
    float inv[4];
    #pragma unroll
    for (int rg = 0; rg < 4; rg++) {
        float ls = lsum[rg];
        ls += __shfl_xor_sync(0xFFFFFFFFu, ls, 1);
        ls += __shfl_xor_sync(0xFFFFFFFFu, ls, 2);
        inv[rg] = 1.f / ls;
    }
    float* ob = out + ((size_t)b * TT) * DKV;
    #pragma unroll
    for (int mt = 0; mt < 2; mt++) {
        #pragma unroll
        for (int h = 0; h < 2; h++) {
            const int row = Q0 + mt * 16 + g + h * 8;
            const float iv = inv[mt * 2 + h];
            #pragma unroll
            for (int n = 0; n < 8; n++) {
                *(float2*)(ob + (size_t)row * DKV + n * 8 + tg * 2) =
                    make_float2(O[mt][n][h * 2] * iv, O[mt][n][h * 2 + 1] * iv);
            }
        }
    }
}

// ---------------------------------------------------------------------------
// kernel_launch — graph-capturable, allocation-free
// ---------------------------------------------------------------------------
extern "C" void kernel_launch(void* const* d_in, const int* in_sizes, int n_in,
                              void* d_out, int out_size) {
    const float* x  = (const float*)d_in[0];
    const float* Wq = (const float*)d_in[1];
    const float* Wk = (const float*)d_in[2];
    const float* Wv = (const float*)d_in[3];
    float* out = (float*)d_out;
    (void)in_sizes; (void)n_in; (void)out_size;

    wconv_kernel<<<(192 * DM + 255) / 256, 256>>>(Wq, Wk, Wv);

    const int proj_smem = SM_ELEMS * (int)sizeof(__half);        // 70 KB
    cudaFuncSetAttribute(proj_mma_kernel,
                         cudaFuncAttributeMaxDynamicSharedMemorySize, proj_smem);
    proj_mma_kernel<<<BT / BM, 256, proj_smem>>>(x);

    const int attn_smem = 2 * KV_SZ * (int)sizeof(__half);       // 72 KB
    cudaFuncSetAttribute(attn_mma_kernel,
                         cudaFuncAttributeMaxDynamicSharedMemorySize, attn_smem);
    attn_mma_kernel<<<BATCH, 256, attn_smem>>>(out);
}

// round 8
// speedup vs baseline: 1.6456x; 1.1386x over previous
#include <cuda_runtime.h>
#include <cuda_fp16.h>
#include <cstdint>

// Problem constants
#define BATCH 256
#define TT    256
#define DM    384
#define DKV   64
#define BT    (BATCH*TT)

// ---------------------------------------------------------------------------
// Scratch
// ---------------------------------------------------------------------------
__device__ float g_q[BT * DKV];
__device__ float g_k[BT * DKV];
__device__ float g_v[BT * DKV];
// W^T packed [192 n][384 k], fp16. n: 0-63=Wq, 64-127=Wk, 128-191=Wv
__device__ __align__(16) __half g_wh[192 * DM];

// ---------------------------------------------------------------------------
// PTX helpers (sm_80-era: mma.sync + ldmatrix, valid at compute_103)
// ---------------------------------------------------------------------------
__device__ __forceinline__ uint32_t smem_u32(const void* p) {
    uint32_t a;
    asm("{ .reg .u64 t; cvta.to.shared.u64 t, %1; cvt.u32.u64 %0, t; }"
        : "=r"(a) : "l"(p));
    return a;
}
__device__ __forceinline__ void ldsm_x4(uint32_t addr, uint32_t* r) {
    asm volatile("ldmatrix.sync.aligned.m8n8.x4.shared.b16 {%0,%1,%2,%3}, [%4];"
                 : "=r"(r[0]), "=r"(r[1]), "=r"(r[2]), "=r"(r[3]) : "r"(addr));
}
__device__ __forceinline__ void ldsm_x4t(uint32_t addr, uint32_t* r) {
    asm volatile("ldmatrix.sync.aligned.m8n8.x4.trans.shared.b16 {%0,%1,%2,%3}, [%4];"
                 : "=r"(r[0]), "=r"(r[1]), "=r"(r[2]), "=r"(r[3]) : "r"(addr));
}
__device__ __forceinline__ void mma_fp16(float* c, const uint32_t* a,
                                         uint32_t b0, uint32_t b1) {
    asm volatile(
        "mma.sync.aligned.m16n8k16.row.col.f32.f16.f16.f32 "
        "{%0,%1,%2,%3}, {%4,%5,%6,%7}, {%8,%9}, {%0,%1,%2,%3};"
        : "+f"(c[0]), "+f"(c[1]), "+f"(c[2]), "+f"(c[3])
        : "r"(a[0]), "r"(a[1]), "r"(a[2]), "r"(a[3]), "r"(b0), "r"(b1));
}
__device__ __forceinline__ float ex2(float x) {
    float y;
    asm("ex2.approx.ftz.f32 %0, %1;" : "=f"(y) : "f"(x));
    return y;
}
// split float2 into packed fp16x2 hi and lo (x = h + l to ~2^-22)
__device__ __forceinline__ void split2h(float x, float y, uint32_t& h, uint32_t& l) {
    __half h0 = __float2half_rn(x), h1 = __float2half_rn(y);
    __half l0 = __float2half_rn(x - __half2float(h0));
    __half l1 = __float2half_rn(y - __half2float(h1));
    __half2 hp = __halves2half2(h0, h1);
    __half2 lp = __halves2half2(l0, l1);
    h = *(uint32_t*)&hp; l = *(uint32_t*)&lp;
}
__device__ __forceinline__ uint32_t pack2h(float x, float y) {
    __half2 hp = __halves2half2(__float2half_rn(x), __float2half_rn(y));
    return *(uint32_t*)&hp;
}

// ---------------------------------------------------------------------------
// Kernel 0: W^T fp16 conversion
// ---------------------------------------------------------------------------
__global__ void wconv_kernel(const float* __restrict__ Wq,
                             const float* __restrict__ Wk,
                             const float* __restrict__ Wv) {
    int idx = blockIdx.x * 256 + threadIdx.x;
    if (idx >= 192 * DM) return;
    int n = idx / DM, k = idx % DM;
    const float* W = (n < 64) ? Wq : (n < 128) ? Wk : Wv;
    g_wh[idx] = __float2half_rn(W[k * DKV + (n & 63)]);
}

// ---------------------------------------------------------------------------
// Kernel 1: fused QKV projection via mma.sync fp16, SINGLE pass (Xh*Wh).
//   BM=128 x BN=192 per CTA, K loop 12 x 32, smem double-buffered.
// ---------------------------------------------------------------------------
#define BM   128
#define BN   192
#define BKS  32
#define NKS  (DM / BKS)
#define PAD  40

#define A_SZ (BM * PAD)          // 5120
#define B_SZ (BN * PAD)          // 7680
#define OFF_AH(buf) ((buf) * A_SZ)
#define OFF_BH(buf) (2 * A_SZ + (buf) * B_SZ)
#define SM_ELEMS    (2 * A_SZ + 2 * B_SZ)            // 25600 fp16 = 50 KB

__global__ void __launch_bounds__(256, 1) proj_mma_kernel(const float* __restrict__ X) {
    extern __shared__ __half sm[];
    const uint32_t sb = smem_u32(sm);

    const int tid    = threadIdx.x;
    const int lane   = tid & 31;
    const int wid    = tid >> 5;
    const int warp_m = wid & 3;          // 4 warps along M: 32 rows each
    const int warp_n = wid >> 2;         // 2 warps along N: 96 cols each
    const int row0   = blockIdx.x * BM;

    float acc[2][12][4];
    #pragma unroll
    for (int m = 0; m < 2; m++)
        #pragma unroll
        for (int n = 0; n < 12; n++)
            #pragma unroll
            for (int j = 0; j < 4; j++) acc[m][n][j] = 0.f;

    float4 xa[4];
    uint4  bhs[3];

    auto load_regs = [&](int ks) {
        const int k0 = ks * BKS;
        #pragma unroll
        for (int i = 0; i < 4; i++) {
            int f  = tid + i * 256;          // 0..1023
            int r  = f >> 3;                 // 0..127
            int c4 = f & 7;
            xa[i] = *(const float4*)(X + (size_t)(row0 + r) * DM + k0 + c4 * 4);
        }
        #pragma unroll
        for (int i = 0; i < 3; i++) {
            int f  = tid + i * 256;          // 0..767
            int r  = f >> 2;                 // 0..191
            int c8 = f & 3;
            bhs[i] = *(const uint4*)(g_wh + r * DM + k0 + c8 * 8);
        }
    };

    auto store_tile = [&](int buf) {
        #pragma unroll
        for (int i = 0; i < 4; i++) {
            int f  = tid + i * 256;
            int r  = f >> 3;
            int c4 = f & 7;
            float4 v = xa[i];
            int e = r * PAD + c4 * 4;
            *(uint2*)(sm + OFF_AH(buf) + e) =
                make_uint2(pack2h(v.x, v.y), pack2h(v.z, v.w));
        }
        #pragma unroll
        for (int i = 0; i < 3; i++) {
            int f  = tid + i * 256;
            int r  = f >> 2;
            int c8 = f & 3;
            *(uint4*)(sm + OFF_BH(buf) + r * PAD + c8 * 8) = bhs[i];
        }
    };

    load_regs(0);
    store_tile(0);
    __syncthreads();

    for (int ks = 0; ks < NKS; ks++) {
        const int cur = ks & 1;
        if (ks + 1 < NKS) load_regs(ks + 1);

        const uint32_t ah_base = sb + OFF_AH(cur) * 2;
        const uint32_t bh_base = sb + OFF_BH(cur) * 2;

        #pragma unroll
        for (int kk = 0; kk < 2; kk++) {
            uint32_t ah[2][4];
            const int arow_l = (lane & 15);
            const int acol   = kk * 16 + ((lane >> 4) << 3);
            #pragma unroll
            for (int mt = 0; mt < 2; mt++) {
                const int arow = warp_m * 32 + mt * 16 + arow_l;
                ldsm_x4(ah_base + (uint32_t)(arow * PAD + acol) * 2, ah[mt]);
            }
            const int brow_l = (lane & 7) + ((lane & 16) >> 1);
            const int bcol   = kk * 16 + (lane & 8);
            #pragma unroll
            for (int g = 0; g < 6; g++) {
                uint32_t bh[4];
                const int brow = warp_n * 96 + g * 16 + brow_l;
                ldsm_x4(bh_base + (uint32_t)(brow * PAD + bcol) * 2, bh);
                #pragma unroll
                for (int mt = 0; mt < 2; mt++) {
                    #pragma unroll
                    for (int h = 0; h < 2; h++) {
                        mma_fp16(acc[mt][g * 2 + h], ah[mt],
                                 bh[h * 2], bh[h * 2 + 1]);
                    }
                }
            }
        }

        if (ks + 1 < NKS) {
            __syncthreads();
            store_tile(cur ^ 1);
            __syncthreads();
        }
    }

    const int gi = lane >> 2;
    const int ti = lane & 3;
    #pragma unroll
    for (int mt = 0; mt < 2; mt++) {
        const int row = row0 + warp_m * 32 + mt * 16 + gi;
        #pragma unroll
        for (int nt = 0; nt < 12; nt++) {
            const int col  = warp_n * 96 + nt * 8 + ti * 2;
            float* dstbase = (col < 64) ? g_q : (col < 128) ? g_k : g_v;
            float* d0 = dstbase + (size_t)row * DKV + (col & 63);
            float* d1 = dstbase + (size_t)(row + 8) * DKV + (col & 63);
            *(float2*)d0 = make_float2(acc[mt][nt][0], acc[mt][nt][1]);
            *(float2*)d1 = make_float2(acc[mt][nt][2], acc[mt][nt][3]);
        }
    }
}

// ---------------------------------------------------------------------------
// Kernel 2: causal attention on mma.sync fp16.
//   K,V single-pass fp16 in smem; Q hi/lo (2-pass QK); P single-pass (PV).
//   CTA = 1 batch, warp = 32 queries, no syncs in the key loop.
// ---------------------------------------------------------------------------
#define APAD 72
#define KV_SZ (TT * APAD)       // 18432 elems per buffer

__global__ void __launch_bounds__(256, 1) attn_mma_kernel(float* __restrict__ out) {
    extern __shared__ __half smk[];
    __half* Kh = smk;
    __half* Vh = smk + KV_SZ;

    const int b    = blockIdx.x;
    const int tid  = threadIdx.x;
    const int lane = tid & 31;
    const int wid  = tid >> 5;

    // ---- prologue: K,V fp32 -> smem fp16 ----
    {
        const float4* Kg = (const float4*)(g_k + (size_t)b * TT * DKV);
        const float4* Vg = (const float4*)(g_v + (size_t)b * TT * DKV);
        #pragma unroll
        for (int i0 = 0; i0 < 16; i0++) {
            int i = tid + i0 * 256;           // 0..4095
            int r = i >> 4, c4 = (i & 15) * 4;
            int e = r * APAD + c4;
            float4 kv = Kg[i];
            *(uint2*)(Kh + e) = make_uint2(pack2h(kv.x, kv.y), pack2h(kv.z, kv.w));
            float4 vv = Vg[i];
            *(uint2*)(Vh + e) = make_uint2(pack2h(vv.x, vv.y), pack2h(vv.z, vv.w));
        }
    }

    // ---- Q fragments (gmem -> regs, hi/lo), scaled by 0.125*log2(e) ----
    const int qb = (wid < 4) ? wid : (11 - wid);   // SMSP balance: pairs sum 288
    const int Q0 = qb * 32;
    const int g  = lane >> 2;
    const int tg = lane & 3;
    const float SC = 0.125f * 1.44269504f;

    uint32_t qh[2][4][4], ql[2][4][4];
    {
        const float* Qb = g_q + ((size_t)b * TT + Q0) * DKV;
        #pragma unroll
        for (int mt = 0; mt < 2; mt++) {
            #pragma unroll
            for (int kk = 0; kk < 4; kk++) {
                const int r0 = mt * 16 + g;
                const int c0 = kk * 16 + tg * 2;
                float2 v00 = *(const float2*)(Qb + r0 * DKV + c0);
                float2 v01 = *(const float2*)(Qb + r0 * DKV + c0 + 8);
                float2 v10 = *(const float2*)(Qb + (r0 + 8) * DKV + c0);
                float2 v11 = *(const float2*)(Qb + (r0 + 8) * DKV + c0 + 8);
                split2h(v00.x * SC, v00.y * SC, qh[mt][kk][0], ql[mt][kk][0]);
                split2h(v10.x * SC, v10.y * SC, qh[mt][kk][1], ql[mt][kk][1]);
                split2h(v01.x * SC, v01.y * SC, qh[mt][kk][2], ql[mt][kk][2]);
                split2h(v11.x * SC, v11.y * SC, qh[mt][kk][3], ql[mt][kk][3]);
            }
        }
    }
    __syncthreads();

    const uint32_t sbKh = smem_u32(Kh);
    const uint32_t sbVh = smem_u32(Vh);

    float m[4] = {-1e30f, -1e30f, -1e30f, -1e30f};
    float lsum[4] = {0.f, 0.f, 0.f, 0.f};
    float O[2][8][4];
    #pragma unroll
    for (int mt = 0; mt < 2; mt++)
        #pragma unroll
        for (int n = 0; n < 8; n++)
            #pragma unroll
            for (int j = 0; j < 4; j++) O[mt][n][j] = 0.f;

    const int krow = (lane & 7) + ((lane & 16) >> 1);   // K/B frag row
    const int koff = (lane & 8);                        // k-offset within k16
    const int vkey = lane & 15;                         // V/B trans frag row
    const int voff = (lane >> 4) << 3;                  // n-offset

    const int nblk = qb * 2 + 2;
    for (int kb = 0; kb < nblk; kb++) {
        const int j0 = kb * 16;
        const bool msk = (kb >= qb * 2);

        // ---- S = Q K^T (Q hi/lo, K single) ----
        float S[2][2][4];
        #pragma unroll
        for (int mt = 0; mt < 2; mt++)
            #pragma unroll
            for (int nt = 0; nt < 2; nt++)
                #pragma unroll
                for (int j = 0; j < 4; j++) S[mt][nt][j] = 0.f;

        const uint32_t kb_h = sbKh + (uint32_t)((j0 + krow) * APAD + koff) * 2;
        #pragma unroll
        for (int kk = 0; kk < 4; kk++) {
            uint32_t bh[4];
            ldsm_x4(kb_h + kk * 32, bh);
            #pragma unroll
            for (int mt = 0; mt < 2; mt++) {
                mma_fp16(S[mt][0], qh[mt][kk], bh[0], bh[1]);
                mma_fp16(S[mt][1], qh[mt][kk], bh[2], bh[3]);
                mma_fp16(S[mt][0], ql[mt][kk], bh[0], bh[1]);
                mma_fp16(S[mt][1], ql[mt][kk], bh[2], bh[3]);
            }
        }

        // ---- causal mask ----
        if (msk) {
            #pragma unroll
            for (int mt = 0; mt < 2; mt++)
                #pragma unroll
                for (int nt = 0; nt < 2; nt++)
                    #pragma unroll
                    for (int j = 0; j < 4; j++) {
                        const int row = Q0 + mt * 16 + g + ((j >> 1) << 3);
                        const int col = j0 + nt * 8 + tg * 2 + (j & 1);
                        if (col > row) S[mt][nt][j] = -1e30f;
                    }
        }

        // ---- online softmax + P frag build (single fp16) ----
        uint32_t pah[2][4];
        #pragma unroll
        for (int mt = 0; mt < 2; mt++) {
            #pragma unroll
            for (int h = 0; h < 2; h++) {
                const int rg = mt * 2 + h;
                float v0 = S[mt][0][h * 2], v1 = S[mt][0][h * 2 + 1];
                float v2 = S[mt][1][h * 2], v3 = S[mt][1][h * 2 + 1];
                float mx = fmaxf(fmaxf(v0, v1), fmaxf(v2, v3));
                mx = fmaxf(mx, __shfl_xor_sync(0xFFFFFFFFu, mx, 1));
                mx = fmaxf(mx, __shfl_xor_sync(0xFFFFFFFFu, mx, 2));
                const float mnew = fmaxf(m[rg], mx);
                const float sc   = ex2(m[rg] - mnew);
                m[rg] = mnew;
                const float p0 = ex2(v0 - mnew), p1 = ex2(v1 - mnew);
                const float p2 = ex2(v2 - mnew), p3 = ex2(v3 - mnew);
                lsum[rg] = lsum[rg] * sc + (p0 + p1 + p2 + p3);
                #pragma unroll
                for (int n = 0; n < 8; n++) {
                    O[mt][n][h * 2]     *= sc;
                    O[mt][n][h * 2 + 1] *= sc;
                }
                pah[mt][h]     = pack2h(p0, p1);
                pah[mt][2 + h] = pack2h(p2, p3);
            }
        }

        // ---- O += P V (P single, V single) ----
        const uint32_t vb_h = sbVh + (uint32_t)((j0 + vkey) * APAD + voff) * 2;
        #pragma unroll
        for (int nc = 0; nc < 4; nc++) {
            uint32_t vh4[4];
            ldsm_x4t(vb_h + nc * 32, vh4);
            #pragma unroll
            for (int mt = 0; mt < 2; mt++) {
                mma_fp16(O[mt][nc * 2],     pah[mt], vh4[0], vh4[1]);
                mma_fp16(O[mt][nc * 2 + 1], pah[mt], vh4[2], vh4[3]);
            }
        }
    }

    // ---- epilogue: quad-reduce l, normalize, store ----
    float inv[4];
    #pragma unroll
    for (int rg = 0; rg < 4; rg++) {
        float ls = lsum[rg];
        ls += __shfl_xor_sync(0xFFFFFFFFu, ls, 1);
        ls += __shfl_xor_sync(0xFFFFFFFFu, ls, 2);
        inv[rg] = 1.f / ls;
    }
    float* ob = out + ((size_t)b * TT) * DKV;
    #pragma unroll
    for (int mt = 0; mt < 2; mt++) {
        #pragma unroll
        for (int h = 0; h < 2; h++) {
            const int row = Q0 + mt * 16 + g + h * 8;
            const float iv = inv[mt * 2 + h];
            #pragma unroll
            for (int n = 0; n < 8; n++) {
                *(float2*)(ob + (size_t)row * DKV + n * 8 + tg * 2) =
                    make_float2(O[mt][n][h * 2] * iv, O[mt][n][h * 2 + 1] * iv);
            }
        }
    }
}

// ---------------------------------------------------------------------------
// kernel_launch — graph-capturable, allocation-free
// ---------------------------------------------------------------------------
extern "C" void kernel_launch(void* const* d_in, const int* in_sizes, int n_in,
                              void* d_out, int out_size) {
    const float* x  = (const float*)d_in[0];
    const float* Wq = (const float*)d_in[1];
    const float* Wk = (const float*)d_in[2];
    const float* Wv = (const float*)d_in[3];
    float* out = (float*)d_out;
    (void)in_sizes; (void)n_in; (void)out_size;

    wconv_kernel<<<(192 * DM + 255) / 256, 256>>>(Wq, Wk, Wv);

    const int proj_smem = SM_ELEMS * (int)sizeof(__half);        // 50 KB
    cudaFuncSetAttribute(proj_mma_kernel,
                         cudaFuncAttributeMaxDynamicSharedMemorySize, proj_smem);
    proj_mma_kernel<<<BT / BM, 256, proj_smem>>>(x);

    const int attn_smem = 2 * KV_SZ * (int)sizeof(__half);       // 72 KB
    cudaFuncSetAttribute(attn_mma_kernel,
                         cudaFuncAttributeMaxDynamicSharedMemorySize, attn_smem);
    attn_mma_kernel<<<BATCH, 256, attn_smem>>>(out);
}

// round 9
// speedup vs baseline: 1.7140x; 1.0416x over previous
#include <cuda_runtime.h>
#include <cuda_fp16.h>
#include <cstdint>

// Problem constants
#define BATCH 256
#define TT    256
#define DM    384
#define DKV   64
#define BT    (BATCH*TT)

// ---------------------------------------------------------------------------
// Scratch
// ---------------------------------------------------------------------------
__device__ float g_q[BT * DKV];
__device__ float g_k[BT * DKV];
__device__ float g_v[BT * DKV];
// W^T packed [192 n][384 k], fp16. n: 0-63=Wq, 64-127=Wk, 128-191=Wv
__device__ __align__(16) __half g_wh[192 * DM];

// ---------------------------------------------------------------------------
// PTX helpers (sm_80-era: mma.sync + ldmatrix + cp.async, valid at compute_103)
// ---------------------------------------------------------------------------
__device__ __forceinline__ uint32_t smem_u32(const void* p) {
    uint32_t a;
    asm("{ .reg .u64 t; cvta.to.shared.u64 t, %1; cvt.u32.u64 %0, t; }"
        : "=r"(a) : "l"(p));
    return a;
}
__device__ __forceinline__ void ldsm_x4(uint32_t addr, uint32_t* r) {
    asm volatile("ldmatrix.sync.aligned.m8n8.x4.shared.b16 {%0,%1,%2,%3}, [%4];"
                 : "=r"(r[0]), "=r"(r[1]), "=r"(r[2]), "=r"(r[3]) : "r"(addr));
}
__device__ __forceinline__ void ldsm_x4t(uint32_t addr, uint32_t* r) {
    asm volatile("ldmatrix.sync.aligned.m8n8.x4.trans.shared.b16 {%0,%1,%2,%3}, [%4];"
                 : "=r"(r[0]), "=r"(r[1]), "=r"(r[2]), "=r"(r[3]) : "r"(addr));
}
__device__ __forceinline__ void mma_fp16(float* c, const uint32_t* a,
                                         uint32_t b0, uint32_t b1) {
    asm volatile(
        "mma.sync.aligned.m16n8k16.row.col.f32.f16.f16.f32 "
        "{%0,%1,%2,%3}, {%4,%5,%6,%7}, {%8,%9}, {%0,%1,%2,%3};"
        : "+f"(c[0]), "+f"(c[1]), "+f"(c[2]), "+f"(c[3])
        : "r"(a[0]), "r"(a[1]), "r"(a[2]), "r"(a[3]), "r"(b0), "r"(b1));
}
__device__ __forceinline__ float ex2(float x) {
    float y;
    asm("ex2.approx.ftz.f32 %0, %1;" : "=f"(y) : "f"(x));
    return y;
}
__device__ __forceinline__ void split2h(float x, float y, uint32_t& h, uint32_t& l) {
    __half h0 = __float2half_rn(x), h1 = __float2half_rn(y);
    __half l0 = __float2half_rn(x - __half2float(h0));
    __half l1 = __float2half_rn(y - __half2float(h1));
    __half2 hp = __halves2half2(h0, h1);
    __half2 lp = __halves2half2(l0, l1);
    h = *(uint32_t*)&hp; l = *(uint32_t*)&lp;
}
__device__ __forceinline__ uint32_t pack2h(float x, float y) {
    __half2 hp = __halves2half2(__float2half_rn(x), __float2half_rn(y));
    return *(uint32_t*)&hp;
}
#define CP_ASYNC16(dst, src) \
    asm volatile("cp.async.cg.shared.global [%0], [%1], 16;" \
                 :: "r"(dst), "l"(src) : "memory")
#define CP_COMMIT() asm volatile("cp.async.commit_group;" ::: "memory")
#define CP_WAIT(n)  asm volatile("cp.async.wait_group %0;" :: "n"(n) : "memory")

// ---------------------------------------------------------------------------
// Kernel 0: W^T fp16 conversion
// ---------------------------------------------------------------------------
__global__ void wconv_kernel(const float* __restrict__ Wq,
                             const float* __restrict__ Wk,
                             const float* __restrict__ Wv) {
    int idx = blockIdx.x * 256 + threadIdx.x;
    if (idx >= 192 * DM) return;
    int n = idx / DM, k = idx % DM;
    const float* W = (n < 64) ? Wq : (n < 128) ? Wk : Wv;
    g_wh[idx] = __float2half_rn(W[k * DKV + (n & 63)]);
}

// ---------------------------------------------------------------------------
// Kernel 1: fused QKV projection, mma.sync fp16 single-pass.
//   BM=128 x BN=192 per CTA, K loop 12 x 32.
//   X: register-staged LDG + fp16 convert + STS (A double buffer).
//   B: cp.async gmem->smem, TRIPLE buffer, prefetch depth 2.
// ---------------------------------------------------------------------------
#define BM   128
#define BN   192
#define BKS  32
#define NKS  (DM / BKS)
#define PAD  40

#define A_SZ (BM * PAD)          // 5120
#define B_SZ (BN * PAD)          // 7680
#define OFF_A(buf)  ((buf) * A_SZ)
#define OFF_B(buf)  (2 * A_SZ + (buf) * B_SZ)
#define SM_ELEMS    (2 * A_SZ + 3 * B_SZ)            // 33280 fp16 = 65 KB

__global__ void __launch_bounds__(256, 1) proj_mma_kernel(const float* __restrict__ X) {
    extern __shared__ __half sm[];
    const uint32_t sb = smem_u32(sm);

    const int tid    = threadIdx.x;
    const int lane   = tid & 31;
    const int wid    = tid >> 5;
    const int warp_m = wid & 3;          // 4 warps along M: 32 rows each
    const int warp_n = wid >> 2;         // 2 warps along N: 96 cols each
    const int row0   = blockIdx.x * BM;

    float acc[2][12][4];
    #pragma unroll
    for (int m = 0; m < 2; m++)
        #pragma unroll
        for (int n = 0; n < 12; n++)
            #pragma unroll
            for (int j = 0; j < 4; j++) acc[m][n][j] = 0.f;

    float4 xa[4];

    // B-tile thread mapping (3 x 16B per thread)
    const int br  = tid >> 2;            // 0..63 base row, strided by 64
    const int bc8 = tid & 3;             // 16B chunk within 64B row

    auto cp_b = [&](int ks, int buf) {
        const int k0 = ks * BKS;
        #pragma unroll
        for (int i = 0; i < 3; i++) {
            int r = br + i * 64;         // 0..191
            uint32_t dst = sb + (uint32_t)(OFF_B(buf) + r * PAD + bc8 * 8) * 2;
            CP_ASYNC16(dst, g_wh + r * DM + k0 + bc8 * 8);
        }
    };
    auto load_x = [&](int ks) {
        const int k0 = ks * BKS;
        #pragma unroll
        for (int i = 0; i < 4; i++) {
            int f  = tid + i * 256;
            int r  = f >> 3;
            int c4 = f & 7;
            xa[i] = *(const float4*)(X + (size_t)(row0 + r) * DM + k0 + c4 * 4);
        }
    };
    auto store_x = [&](int buf) {
        #pragma unroll
        for (int i = 0; i < 4; i++) {
            int f  = tid + i * 256;
            int r  = f >> 3;
            int c4 = f & 7;
            float4 v = xa[i];
            *(uint2*)(sm + OFF_A(buf) + r * PAD + c4 * 4) =
                make_uint2(pack2h(v.x, v.y), pack2h(v.z, v.w));
        }
    };

    // ---- prologue: prefetch B(0), B(1); stage X(0) ----
    cp_b(0, 0); CP_COMMIT();
    cp_b(1, 1); CP_COMMIT();
    load_x(0);
    store_x(0);
    CP_WAIT(1);                      // B(0) landed
    __syncthreads();

    for (int ks = 0; ks < NKS; ks++) {
        const int acur = ks & 1;
        const int bcur = ks % 3;

        if (ks + 2 < NKS) { cp_b(ks + 2, (ks + 2) % 3); CP_COMMIT(); }
        if (ks + 1 < NKS) load_x(ks + 1);

        const uint32_t a_base = sb + OFF_A(acur) * 2;
        const uint32_t b_base = sb + OFF_B(bcur) * 2;

        #pragma unroll
        for (int kk = 0; kk < 2; kk++) {
            uint32_t ah[2][4];
            const int arow_l = (lane & 15);
            const int acol   = kk * 16 + ((lane >> 4) << 3);
            #pragma unroll
            for (int mt = 0; mt < 2; mt++) {
                const int arow = warp_m * 32 + mt * 16 + arow_l;
                ldsm_x4(a_base + (uint32_t)(arow * PAD + acol) * 2, ah[mt]);
            }
            const int brow_l = (lane & 7) + ((lane & 16) >> 1);
            const int bcol   = kk * 16 + (lane & 8);
            #pragma unroll
            for (int g = 0; g < 6; g++) {
                uint32_t bh[4];
                const int brow = warp_n * 96 + g * 16 + brow_l;
                ldsm_x4(b_base + (uint32_t)(brow * PAD + bcol) * 2, bh);
                #pragma unroll
                for (int mt = 0; mt < 2; mt++) {
                    #pragma unroll
                    for (int h = 0; h < 2; h++) {
                        mma_fp16(acc[mt][g * 2 + h], ah[mt],
                                 bh[h * 2], bh[h * 2 + 1]);
                    }
                }
            }
        }

        if (ks + 1 < NKS) {
            __syncthreads();                 // A buf acur^1 free; B(ks) readers done
            store_x(acur ^ 1);
            if (ks + 2 < NKS) { CP_WAIT(1); }   // B(ks+1) landed, B(ks+2) may fly
            else              { CP_WAIT(0); }   // last prefetch: drain all
            __syncthreads();
        }
    }

    const int gi = lane >> 2;
    const int ti = lane & 3;
    #pragma unroll
    for (int mt = 0; mt < 2; mt++) {
        const int row = row0 + warp_m * 32 + mt * 16 + gi;
        #pragma unroll
        for (int nt = 0; nt < 12; nt++) {
            const int col  = warp_n * 96 + nt * 8 + ti * 2;
            float* dstbase = (col < 64) ? g_q : (col < 128) ? g_k : g_v;
            float* d0 = dstbase + (size_t)row * DKV + (col & 63);
            float* d1 = dstbase + (size_t)(row + 8) * DKV + (col & 63);
            *(float2*)d0 = make_float2(acc[mt][nt][0], acc[mt][nt][1]);
            *(float2*)d1 = make_float2(acc[mt][nt][2], acc[mt][nt][3]);
        }
    }
}

// ---------------------------------------------------------------------------
// Kernel 2: causal attention, mma.sync fp16, 32-key softmax rounds.
//   K,V fp16 in smem; Q hi/lo (2-pass QK); P single-pass PV.
//   CTA = 1 batch, warp = 32 queries; softmax bookkeeping once per 32 keys.
// ---------------------------------------------------------------------------
#define APAD 72
#define KV_SZ (TT * APAD)       // 18432 elems per buffer

__global__ void __launch_bounds__(256, 1) attn_mma_kernel(float* __restrict__ out) {
    extern __shared__ __half smk[];
    __half* Kh = smk;
    __half* Vh = smk + KV_SZ;

    const int b    = blockIdx.x;
    const int tid  = threadIdx.x;
    const int lane = tid & 31;
    const int wid  = tid >> 5;

    // ---- prologue: K,V fp32 -> smem fp16 ----
    {
        const float4* Kg = (const float4*)(g_k + (size_t)b * TT * DKV);
        const float4* Vg = (const float4*)(g_v + (size_t)b * TT * DKV);
        #pragma unroll
        for (int i0 = 0; i0 < 16; i0++) {
            int i = tid + i0 * 256;
            int r = i >> 4, c4 = (i & 15) * 4;
            int e = r * APAD + c4;
            float4 kv = Kg[i];
            *(uint2*)(Kh + e) = make_uint2(pack2h(kv.x, kv.y), pack2h(kv.z, kv.w));
            float4 vv = Vg[i];
            *(uint2*)(Vh + e) = make_uint2(pack2h(vv.x, vv.y), pack2h(vv.z, vv.w));
        }
    }

    // ---- Q fragments (gmem -> regs, hi/lo), scaled by 0.125*log2(e) ----
    const int qb = (wid < 4) ? wid : (11 - wid);   // SMSP balance: pairs sum 9 rounds
    const int Q0 = qb * 32;
    const int g  = lane >> 2;
    const int tg = lane & 3;
    const float SC = 0.125f * 1.44269504f;

    uint32_t qh[2][4][4], ql[2][4][4];
    {
        const float* Qb = g_q + ((size_t)b * TT + Q0) * DKV;
        #pragma unroll
        for (int mt = 0; mt < 2; mt++) {
            #pragma unroll
            for (int kk = 0; kk < 4; kk++) {
                const int r0 = mt * 16 + g;
                const int c0 = kk * 16 + tg * 2;
                float2 v00 = *(const float2*)(Qb + r0 * DKV + c0);
                float2 v01 = *(const float2*)(Qb + r0 * DKV + c0 + 8);
                float2 v10 = *(const float2*)(Qb + (r0 + 8) * DKV + c0);
                float2 v11 = *(const float2*)(Qb + (r0 + 8) * DKV + c0 + 8);
                split2h(v00.x * SC, v00.y * SC, qh[mt][kk][0], ql[mt][kk][0]);
                split2h(v10.x * SC, v10.y * SC, qh[mt][kk][1], ql[mt][kk][1]);
                split2h(v01.x * SC, v01.y * SC, qh[mt][kk][2], ql[mt][kk][2]);
                split2h(v11.x * SC, v11.y * SC, qh[mt][kk][3], ql[mt][kk][3]);
            }
        }
    }
    __syncthreads();

    const uint32_t sbKh = smem_u32(Kh);
    const uint32_t sbVh = smem_u32(Vh);

    float m[4] = {-1e30f, -1e30f, -1e30f, -1e30f};
    float lsum[4] = {0.f, 0.f, 0.f, 0.f};
    float O[2][8][4];
    #pragma unroll
    for (int mt = 0; mt < 2; mt++)
        #pragma unroll
        for (int n = 0; n < 8; n++)
            #pragma unroll
            for (int j = 0; j < 4; j++) O[mt][n][j] = 0.f;

    const int krow = (lane & 7) + ((lane & 16) >> 1);   // K frag row
    const int koff = (lane & 8);                        // k-offset within k16
    const int vkey = lane & 15;                         // V trans frag row
    const int voff = (lane >> 4) << 3;                  // n-offset

    const int nrounds = qb + 1;                         // 32 keys per round
    for (int kr = 0; kr < nrounds; kr++) {
        const int j0 = kr * 32;
        const bool msk = (kr == qb);

        // ---- S = Q K^T over 32 keys (Q hi/lo, K single) ----
        float S[2][4][4];
        #pragma unroll
        for (int mt = 0; mt < 2; mt++)
            #pragma unroll
            for (int nt = 0; nt < 4; nt++)
                #pragma unroll
                for (int j = 0; j < 4; j++) S[mt][nt][j] = 0.f;

        const uint32_t kb0 = sbKh + (uint32_t)((j0 + krow) * APAD + koff) * 2;
        const uint32_t kb1 = sbKh + (uint32_t)((j0 + 16 + krow) * APAD + koff) * 2;
        #pragma unroll
        for (int kk = 0; kk < 4; kk++) {
            uint32_t b0[4], b1[4];
            ldsm_x4(kb0 + kk * 32, b0);
            ldsm_x4(kb1 + kk * 32, b1);
            #pragma unroll
            for (int mt = 0; mt < 2; mt++) {
                mma_fp16(S[mt][0], qh[mt][kk], b0[0], b0[1]);
                mma_fp16(S[mt][1], qh[mt][kk], b0[2], b0[3]);
                mma_fp16(S[mt][2], qh[mt][kk], b1[0], b1[1]);
                mma_fp16(S[mt][3], qh[mt][kk], b1[2], b1[3]);
                mma_fp16(S[mt][0], ql[mt][kk], b0[0], b0[1]);
                mma_fp16(S[mt][1], ql[mt][kk], b0[2], b0[3]);
                mma_fp16(S[mt][2], ql[mt][kk], b1[0], b1[1]);
                mma_fp16(S[mt][3], ql[mt][kk], b1[2], b1[3]);
            }
        }

        // ---- causal mask (last round only) ----
        if (msk) {
            #pragma unroll
            for (int mt = 0; mt < 2; mt++)
                #pragma unroll
                for (int nt = 0; nt < 4; nt++)
                    #pragma unroll
                    for (int j = 0; j < 4; j++) {
                        const int row = Q0 + mt * 16 + g + ((j >> 1) << 3);
                        const int col = j0 + nt * 8 + tg * 2 + (j & 1);
                        if (col > row) S[mt][nt][j] = -1e30f;
                    }
        }

        // ---- online softmax over 32 keys + P frags ----
        uint32_t pa0[2][4], pa1[2][4];
        #pragma unroll
        for (int mt = 0; mt < 2; mt++) {
            #pragma unroll
            for (int h = 0; h < 2; h++) {
                const int rg = mt * 2 + h;
                float v0 = S[mt][0][h * 2], v1 = S[mt][0][h * 2 + 1];
                float v2 = S[mt][1][h * 2], v3 = S[mt][1][h * 2 + 1];
                float v4 = S[mt][2][h * 2], v5 = S[mt][2][h * 2 + 1];
                float v6 = S[mt][3][h * 2], v7 = S[mt][3][h * 2 + 1];
                float mx = fmaxf(fmaxf(fmaxf(v0, v1), fmaxf(v2, v3)),
                                 fmaxf(fmaxf(v4, v5), fmaxf(v6, v7)));
                mx = fmaxf(mx, __shfl_xor_sync(0xFFFFFFFFu, mx, 1));
                mx = fmaxf(mx, __shfl_xor_sync(0xFFFFFFFFu, mx, 2));
                const float mnew = fmaxf(m[rg], mx);
                const float sc   = ex2(m[rg] - mnew);
                m[rg] = mnew;
                const float p0 = ex2(v0 - mnew), p1 = ex2(v1 - mnew);
                const float p2 = ex2(v2 - mnew), p3 = ex2(v3 - mnew);
                const float p4 = ex2(v4 - mnew), p5 = ex2(v5 - mnew);
                const float p6 = ex2(v6 - mnew), p7 = ex2(v7 - mnew);
                lsum[rg] = lsum[rg] * sc +
                           ((p0 + p1) + (p2 + p3)) + ((p4 + p5) + (p6 + p7));
                #pragma unroll
                for (int n = 0; n < 8; n++) {
                    O[mt][n][h * 2]     *= sc;
                    O[mt][n][h * 2 + 1] *= sc;
                }
                pa0[mt][h]     = pack2h(p0, p1);
                pa0[mt][2 + h] = pack2h(p2, p3);
                pa1[mt][h]     = pack2h(p4, p5);
                pa1[mt][2 + h] = pack2h(p6, p7);
            }
        }

        // ---- O += P V over 32 keys (single pass) ----
        const uint32_t vb0 = sbVh + (uint32_t)((j0 + vkey) * APAD + voff) * 2;
        const uint32_t vb1 = sbVh + (uint32_t)((j0 + 16 + vkey) * APAD + voff) * 2;
        #pragma unroll
        for (int nc = 0; nc < 4; nc++) {
            uint32_t v0[4], v1[4];
            ldsm_x4t(vb0 + nc * 32, v0);
            ldsm_x4t(vb1 + nc * 32, v1);
            #pragma unroll
            for (int mt = 0; mt < 2; mt++) {
                mma_fp16(O[mt][nc * 2],     pa0[mt], v0[0], v0[1]);
                mma_fp16(O[mt][nc * 2 + 1], pa0[mt], v0[2], v0[3]);
                mma_fp16(O[mt][nc * 2],     pa1[mt], v1[0], v1[1]);
                mma_fp16(O[mt][nc * 2 + 1], pa1[mt], v1[2], v1[3]);
            }
        }
    }

    // ---- epilogue: quad-reduce l, normalize, store ----
    float inv[4];
    #pragma unroll
    for (int rg = 0; rg < 4; rg++) {
        float ls = lsum[rg];
        ls += __shfl_xor_sync(0xFFFFFFFFu, ls, 1);
        ls += __shfl_xor_sync(0xFFFFFFFFu, ls, 2);
        inv[rg] = 1.f / ls;
    }
    float* ob = out + ((size_t)b * TT) * DKV;
    #pragma unroll
    for (int mt = 0; mt < 2; mt++) {
        #pragma unroll
        for (int h = 0; h < 2; h++) {
            const int row = Q0 + mt * 16 + g + h * 8;
            const float iv = inv[mt * 2 + h];
            #pragma unroll
            for (int n = 0; n < 8; n++) {
                *(float2*)(ob + (size_t)row * DKV + n * 8 + tg * 2) =
                    make_float2(O[mt][n][h * 2] * iv, O[mt][n][h * 2 + 1] * iv);
            }
        }
    }
}

// ---------------------------------------------------------------------------
// kernel_launch — graph-capturable, allocation-free
// ---------------------------------------------------------------------------
extern "C" void kernel_launch(void* const* d_in, const int* in_sizes, int n_in,
                              void* d_out, int out_size) {
    const float* x  = (const float*)d_in[0];
    const float* Wq = (const float*)d_in[1];
    const float* Wk = (const float*)d_in[2];
    const float* Wv = (const float*)d_in[3];
    float* out = (float*)d_out;
    (void)in_sizes; (void)n_in; (void)out_size;

    wconv_kernel<<<(192 * DM + 255) / 256, 256>>>(Wq, Wk, Wv);

    const int proj_smem = SM_ELEMS * (int)sizeof(__half);        // 65 KB
    cudaFuncSetAttribute(proj_mma_kernel,
                         cudaFuncAttributeMaxDynamicSharedMemorySize, proj_smem);
    proj_mma_kernel<<<BT / BM, 256, proj_smem>>>(x);

    const int attn_smem = 2 * KV_SZ * (int)sizeof(__half);       // 72 KB
    cudaFuncSetAttribute(attn_mma_kernel,
                         cudaFuncAttributeMaxDynamicSharedMemorySize, attn_smem);
    attn_mma_kernel<<<BATCH, 256, attn_smem>>>(out);
}

// round 10
// speedup vs baseline: 1.7619x; 1.0280x over previous
#include <cuda_runtime.h>
#include <cuda_fp16.h>
#include <cstdint>

// Problem constants
#define BATCH 256
#define TT    256
#define DM    384
#define DKV   64
#define BT    (BATCH*TT)

// ---------------------------------------------------------------------------
// Scratch
// ---------------------------------------------------------------------------
__device__ float g_q[BT * DKV];                       // q stays fp32 (hi/lo source)
__device__ __align__(16) __half g_kh[BT * DKV];       // k in fp16
__device__ __align__(16) __half g_vh[BT * DKV];       // v in fp16
// W^T packed [192 n][384 k], fp16. n: 0-63=Wq, 64-127=Wk, 128-191=Wv
__device__ __align__(16) __half g_wh[192 * DM];

// ---------------------------------------------------------------------------
// PTX helpers (sm_80-era: mma.sync + ldmatrix + cp.async, valid at compute_103)
// ---------------------------------------------------------------------------
__device__ __forceinline__ uint32_t smem_u32(const void* p) {
    uint32_t a;
    asm("{ .reg .u64 t; cvta.to.shared.u64 t, %1; cvt.u32.u64 %0, t; }"
        : "=r"(a) : "l"(p));
    return a;
}
__device__ __forceinline__ void ldsm_x4(uint32_t addr, uint32_t* r) {
    asm volatile("ldmatrix.sync.aligned.m8n8.x4.shared.b16 {%0,%1,%2,%3}, [%4];"
                 : "=r"(r[0]), "=r"(r[1]), "=r"(r[2]), "=r"(r[3]) : "r"(addr));
}
__device__ __forceinline__ void ldsm_x4t(uint32_t addr, uint32_t* r) {
    asm volatile("ldmatrix.sync.aligned.m8n8.x4.trans.shared.b16 {%0,%1,%2,%3}, [%4];"
                 : "=r"(r[0]), "=r"(r[1]), "=r"(r[2]), "=r"(r[3]) : "r"(addr));
}
__device__ __forceinline__ void mma_fp16(float* c, const uint32_t* a,
                                         uint32_t b0, uint32_t b1) {
    asm volatile(
        "mma.sync.aligned.m16n8k16.row.col.f32.f16.f16.f32 "
        "{%0,%1,%2,%3}, {%4,%5,%6,%7}, {%8,%9}, {%0,%1,%2,%3};"
        : "+f"(c[0]), "+f"(c[1]), "+f"(c[2]), "+f"(c[3])
        : "r"(a[0]), "r"(a[1]), "r"(a[2]), "r"(a[3]), "r"(b0), "r"(b1));
}
__device__ __forceinline__ float ex2(float x) {
    float y;
    asm("ex2.approx.ftz.f32 %0, %1;" : "=f"(y) : "f"(x));
    return y;
}
__device__ __forceinline__ void split2h(float x, float y, uint32_t& h, uint32_t& l) {
    __half h0 = __float2half_rn(x), h1 = __float2half_rn(y);
    __half l0 = __float2half_rn(x - __half2float(h0));
    __half l1 = __float2half_rn(y - __half2float(h1));
    __half2 hp = __halves2half2(h0, h1);
    __half2 lp = __halves2half2(l0, l1);
    h = *(uint32_t*)&hp; l = *(uint32_t*)&lp;
}
__device__ __forceinline__ uint32_t pack2h(float x, float y) {
    __half2 hp = __halves2half2(__float2half_rn(x), __float2half_rn(y));
    return *(uint32_t*)&hp;
}
#define CP_ASYNC16(dst, src) \
    asm volatile("cp.async.cg.shared.global [%0], [%1], 16;" \
                 :: "r"(dst), "l"(src) : "memory")
#define CP_COMMIT() asm volatile("cp.async.commit_group;" ::: "memory")
#define CP_WAIT(n)  asm volatile("cp.async.wait_group %0;" :: "n"(n) : "memory")

// ---------------------------------------------------------------------------
// Kernel 0: W^T fp16 conversion, coalesced reads via smem transpose.
//   Block: 32 k x 64 n tile of one weight matrix. Grid 36 = 12 ktiles x 3 mats.
// ---------------------------------------------------------------------------
__global__ void wconv_kernel(const float* __restrict__ Wq,
                             const float* __restrict__ Wk,
                             const float* __restrict__ Wv) {
    __shared__ float t[32][65];
    const int mat = blockIdx.x / 12;          // 0..2
    const int k0  = (blockIdx.x % 12) * 32;
    const float* W = (mat == 0) ? Wq : (mat == 1) ? Wk : Wv;
    const int tid = threadIdx.x;

    // read: 8 rows of W (k), 64 n each — coalesced
    {
        const int n  = tid & 63;
        const int kl = tid >> 6;              // 0..3
        #pragma unroll
        for (int i = 0; i < 8; i++) {
            const int k = kl + i * 4;
            t[k][n] = W[(size_t)(k0 + k) * DKV + n];
        }
    }
    __syncthreads();
    // write: g_wh[(mat*64+n)*DM + k0 + k], 32 consecutive k per thread-row
    {
        const int kl = tid & 31;
        const int nl = tid >> 5;              // 0..7
        #pragma unroll
        for (int i = 0; i < 8; i++) {
            const int n = nl + i * 8;
            g_wh[(size_t)(mat * 64 + n) * DM + k0 + kl] = __float2half_rn(t[kl][n]);
        }
    }
}

// ---------------------------------------------------------------------------
// Kernel 1: fused QKV projection, mma.sync fp16 single-pass.
//   BM=128 x BN=192 per CTA, K loop 12 x 32.
//   A: triple buffer (reg-staged LDG + convert + STS), ONE sync per stage.
//   B: cp.async triple buffer, prefetch depth 2.
//   Epilogue: q -> fp32, k/v -> fp16.
// ---------------------------------------------------------------------------
#define BM   128
#define BN   192
#define BKS  32
#define NKS  (DM / BKS)
#define PAD  40

#define A_SZ (BM * PAD)          // 5120
#define B_SZ (BN * PAD)          // 7680
#define OFF_A(buf)  ((buf) * A_SZ)
#define OFF_B(buf)  (3 * A_SZ + (buf) * B_SZ)
#define SM_ELEMS    (3 * A_SZ + 3 * B_SZ)            // 38400 fp16 = 76.8 KB

__global__ void __launch_bounds__(256, 1) proj_mma_kernel(const float* __restrict__ X) {
    extern __shared__ __half sm[];
    const uint32_t sb = smem_u32(sm);

    const int tid    = threadIdx.x;
    const int lane   = tid & 31;
    const int wid    = tid >> 5;
    const int warp_m = wid & 3;          // 4 warps along M: 32 rows each
    const int warp_n = wid >> 2;         // 2 warps along N: 96 cols each
    const int row0   = blockIdx.x * BM;

    float acc[2][12][4];
    #pragma unroll
    for (int m = 0; m < 2; m++)
        #pragma unroll
        for (int n = 0; n < 12; n++)
            #pragma unroll
            for (int j = 0; j < 4; j++) acc[m][n][j] = 0.f;

    float4 xa[4];

    const int br  = tid >> 2;            // B rows, strided by 64
    const int bc8 = tid & 3;

    auto cp_b = [&](int ks, int buf) {
        const int k0 = ks * BKS;
        #pragma unroll
        for (int i = 0; i < 3; i++) {
            int r = br + i * 64;
            uint32_t dst = sb + (uint32_t)(OFF_B(buf) + r * PAD + bc8 * 8) * 2;
            CP_ASYNC16(dst, g_wh + r * DM + k0 + bc8 * 8);
        }
    };
    auto load_x = [&](int ks) {
        const int k0 = ks * BKS;
        #pragma unroll
        for (int i = 0; i < 4; i++) {
            int f  = tid + i * 256;
            int r  = f >> 3;
            int c4 = f & 7;
            xa[i] = *(const float4*)(X + (size_t)(row0 + r) * DM + k0 + c4 * 4);
        }
    };
    auto store_x = [&](int buf) {
        #pragma unroll
        for (int i = 0; i < 4; i++) {
            int f  = tid + i * 256;
            int r  = f >> 3;
            int c4 = f & 7;
            float4 v = xa[i];
            *(uint2*)(sm + OFF_A(buf) + r * PAD + c4 * 4) =
                make_uint2(pack2h(v.x, v.y), pack2h(v.z, v.w));
        }
    };

    // ---- prologue ----
    cp_b(0, 0); CP_COMMIT();
    cp_b(1, 1); CP_COMMIT();
    load_x(0);
    store_x(0);
    CP_WAIT(1);                      // B(0) landed
    __syncthreads();

    for (int ks = 0; ks < NKS; ks++) {
        if (ks + 2 < NKS) { cp_b(ks + 2, (ks + 2) % 3); CP_COMMIT(); }
        if (ks + 1 < NKS) load_x(ks + 1);

        const uint32_t a_base = sb + OFF_A(ks % 3) * 2;
        const uint32_t b_base = sb + OFF_B(ks % 3) * 2;

        #pragma unroll
        for (int kk = 0; kk < 2; kk++) {
            uint32_t ah[2][4];
            const int arow_l = (lane & 15);
            const int acol   = kk * 16 + ((lane >> 4) << 3);
            #pragma unroll
            for (int mt = 0; mt < 2; mt++) {
                const int arow = warp_m * 32 + mt * 16 + arow_l;
                ldsm_x4(a_base + (uint32_t)(arow * PAD + acol) * 2, ah[mt]);
            }
            const int brow_l = (lane & 7) + ((lane & 16) >> 1);
            const int bcol   = kk * 16 + (lane & 8);
            #pragma unroll
            for (int g = 0; g < 6; g++) {
                uint32_t bh[4];
                const int brow = warp_n * 96 + g * 16 + brow_l;
                ldsm_x4(b_base + (uint32_t)(brow * PAD + bcol) * 2, bh);
                #pragma unroll
                for (int mt = 0; mt < 2; mt++) {
                    #pragma unroll
                    for (int h = 0; h < 2; h++) {
                        mma_fp16(acc[mt][g * 2 + h], ah[mt],
                                 bh[h * 2], bh[h * 2 + 1]);
                    }
                }
            }
        }

        if (ks + 1 < NKS) {
            store_x((ks + 1) % 3);           // triple buffer: no collision pre-barrier
            if (ks + 2 < NKS) { CP_WAIT(1); }
            else              { CP_WAIT(0); }
            __syncthreads();                 // single barrier per stage
        }
    }

    // ---- epilogue: q -> fp32, k/v -> fp16 ----
    const int gi = lane >> 2;
    const int ti = lane & 3;
    #pragma unroll
    for (int mt = 0; mt < 2; mt++) {
        const int row = row0 + warp_m * 32 + mt * 16 + gi;
        #pragma unroll
        for (int nt = 0; nt < 12; nt++) {
            const int col = warp_n * 96 + nt * 8 + ti * 2;
            if (col < 64) {
                float* d0 = g_q + (size_t)row * DKV + col;
                float* d1 = g_q + (size_t)(row + 8) * DKV + col;
                *(float2*)d0 = make_float2(acc[mt][nt][0], acc[mt][nt][1]);
                *(float2*)d1 = make_float2(acc[mt][nt][2], acc[mt][nt][3]);
            } else {
                __half* dstbase = (col < 128) ? g_kh : g_vh;
                *(uint32_t*)(dstbase + (size_t)row * DKV + (col & 63)) =
                    pack2h(acc[mt][nt][0], acc[mt][nt][1]);
                *(uint32_t*)(dstbase + (size_t)(row + 8) * DKV + (col & 63)) =
                    pack2h(acc[mt][nt][2], acc[mt][nt][3]);
            }
        }
    }
}

// ---------------------------------------------------------------------------
// Kernel 2: causal attention, mma.sync fp16, 32-key softmax rounds.
//   K,V fp16 in gmem -> cp.async straight to smem (overlapped with Q load).
//   Q hi/lo (2-pass QK); P single-pass PV. CTA = 1 batch, warp = 32 queries.
// ---------------------------------------------------------------------------
#define APAD 72
#define KV_SZ (TT * APAD)       // 18432 elems per buffer

__global__ void __launch_bounds__(256, 1) attn_mma_kernel(float* __restrict__ out) {
    extern __shared__ __half smk[];
    __half* Kh = smk;
    __half* Vh = smk + KV_SZ;

    const int b    = blockIdx.x;
    const int tid  = threadIdx.x;
    const int lane = tid & 31;
    const int wid  = tid >> 5;

    const uint32_t sbKh = smem_u32(Kh);
    const uint32_t sbVh = smem_u32(Vh);

    // ---- prologue: K,V fp16 gmem -> smem via cp.async (no conversion) ----
    {
        const __half* Kg = g_kh + (size_t)b * TT * DKV;
        const __half* Vg = g_vh + (size_t)b * TT * DKV;
        #pragma unroll
        for (int i0 = 0; i0 < 8; i0++) {
            int i = tid + i0 * 256;           // 0..2047 chunk id (16B chunks)
            int r = i >> 3, c = i & 7;
            uint32_t off = (uint32_t)(r * APAD + c * 8) * 2;
            CP_ASYNC16(sbKh + off, Kg + r * DKV + c * 8);
            CP_ASYNC16(sbVh + off, Vg + r * DKV + c * 8);
        }
        CP_COMMIT();
    }

    // ---- Q fragments (gmem -> regs, hi/lo), overlapped with cp.async ----
    const int qb = (wid < 4) ? wid : (11 - wid);   // SMSP balance: 9 rounds each
    const int Q0 = qb * 32;
    const int g  = lane >> 2;
    const int tg = lane & 3;
    const float SC = 0.125f * 1.44269504f;

    uint32_t qh[2][4][4], ql[2][4][4];
    {
        const float* Qb = g_q + ((size_t)b * TT + Q0) * DKV;
        #pragma unroll
        for (int mt = 0; mt < 2; mt++) {
            #pragma unroll
            for (int kk = 0; kk < 4; kk++) {
                const int r0 = mt * 16 + g;
                const int c0 = kk * 16 + tg * 2;
                float2 v00 = *(const float2*)(Qb + r0 * DKV + c0);
                float2 v01 = *(const float2*)(Qb + r0 * DKV + c0 + 8);
                float2 v10 = *(const float2*)(Qb + (r0 + 8) * DKV + c0);
                float2 v11 = *(const float2*)(Qb + (r0 + 8) * DKV + c0 + 8);
                split2h(v00.x * SC, v00.y * SC, qh[mt][kk][0], ql[mt][kk][0]);
                split2h(v10.x * SC, v10.y * SC, qh[mt][kk][1], ql[mt][kk][1]);
                split2h(v01.x * SC, v01.y * SC, qh[mt][kk][2], ql[mt][kk][2]);
                split2h(v11.x * SC, v11.y * SC, qh[mt][kk][3], ql[mt][kk][3]);
            }
        }
    }
    CP_WAIT(0);
    __syncthreads();

    float m[4] = {-1e30f, -1e30f, -1e30f, -1e30f};
    float lsum[4] = {0.f, 0.f, 0.f, 0.f};
    float O[2][8][4];
    #pragma unroll
    for (int mt = 0; mt < 2; mt++)
        #pragma unroll
        for (int n = 0; n < 8; n++)
            #pragma unroll
            for (int j = 0; j < 4; j++) O[mt][n][j] = 0.f;

    const int krow = (lane & 7) + ((lane & 16) >> 1);
    const int koff = (lane & 8);
    const int vkey = lane & 15;
    const int voff = (lane >> 4) << 3;

    const int nrounds = qb + 1;                         // 32 keys per round
    for (int kr = 0; kr < nrounds; kr++) {
        const int j0 = kr * 32;
        const bool msk = (kr == qb);

        float S[2][4][4];
        #pragma unroll
        for (int mt = 0; mt < 2; mt++)
            #pragma unroll
            for (int nt = 0; nt < 4; nt++)
                #pragma unroll
                for (int j = 0; j < 4; j++) S[mt][nt][j] = 0.f;

        const uint32_t kb0 = sbKh + (uint32_t)((j0 + krow) * APAD + koff) * 2;
        const uint32_t kb1 = sbKh + (uint32_t)((j0 + 16 + krow) * APAD + koff) * 2;
        #pragma unroll
        for (int kk = 0; kk < 4; kk++) {
            uint32_t b0[4], b1[4];
            ldsm_x4(kb0 + kk * 32, b0);
            ldsm_x4(kb1 + kk * 32, b1);
            #pragma unroll
            for (int mt = 0; mt < 2; mt++) {
                mma_fp16(S[mt][0], qh[mt][kk], b0[0], b0[1]);
                mma_fp16(S[mt][1], qh[mt][kk], b0[2], b0[3]);
                mma_fp16(S[mt][2], qh[mt][kk], b1[0], b1[1]);
                mma_fp16(S[mt][3], qh[mt][kk], b1[2], b1[3]);
                mma_fp16(S[mt][0], ql[mt][kk], b0[0], b0[1]);
                mma_fp16(S[mt][1], ql[mt][kk], b0[2], b0[3]);
                mma_fp16(S[mt][2], ql[mt][kk], b1[0], b1[1]);
                mma_fp16(S[mt][3], ql[mt][kk], b1[2], b1[3]);
            }
        }

        if (msk) {
            #pragma unroll
            for (int mt = 0; mt < 2; mt++)
                #pragma unroll
                for (int nt = 0; nt < 4; nt++)
                    #pragma unroll
                    for (int j = 0; j < 4; j++) {
                        const int row = Q0 + mt * 16 + g + ((j >> 1) << 3);
                        const int col = j0 + nt * 8 + tg * 2 + (j & 1);
                        if (col > row) S[mt][nt][j] = -1e30f;
                    }
        }

        uint32_t pa0[2][4], pa1[2][4];
        #pragma unroll
        for (int mt = 0; mt < 2; mt++) {
            #pragma unroll
            for (int h = 0; h < 2; h++) {
                const int rg = mt * 2 + h;
                float v0 = S[mt][0][h * 2], v1 = S[mt][0][h * 2 + 1];
                float v2 = S[mt][1][h * 2], v3 = S[mt][1][h * 2 + 1];
                float v4 = S[mt][2][h * 2], v5 = S[mt][2][h * 2 + 1];
                float v6 = S[mt][3][h * 2], v7 = S[mt][3][h * 2 + 1];
                float mx = fmaxf(fmaxf(fmaxf(v0, v1), fmaxf(v2, v3)),
                                 fmaxf(fmaxf(v4, v5), fmaxf(v6, v7)));
                mx = fmaxf(mx, __shfl_xor_sync(0xFFFFFFFFu, mx, 1));
                mx = fmaxf(mx, __shfl_xor_sync(0xFFFFFFFFu, mx, 2));
                const float mnew = fmaxf(m[rg], mx);
                const float sc   = ex2(m[rg] - mnew);
                m[rg] = mnew;
                const float p0 = ex2(v0 - mnew), p1 = ex2(v1 - mnew);
                const float p2 = ex2(v2 - mnew), p3 = ex2(v3 - mnew);
                const float p4 = ex2(v4 - mnew), p5 = ex2(v5 - mnew);
                const float p6 = ex2(v6 - mnew), p7 = ex2(v7 - mnew);
                lsum[rg] = lsum[rg] * sc +
                           ((p0 + p1) + (p2 + p3)) + ((p4 + p5) + (p6 + p7));
                #pragma unroll
                for (int n = 0; n < 8; n++) {
                    O[mt][n][h * 2]     *= sc;
                    O[mt][n][h * 2 + 1] *= sc;
                }
                pa0[mt][h]     = pack2h(p0, p1);
                pa0[mt][2 + h] = pack2h(p2, p3);
                pa1[mt][h]     = pack2h(p4, p5);
                pa1[mt][2 + h] = pack2h(p6, p7);
            }
        }

        const uint32_t vb0 = sbVh + (uint32_t)((j0 + vkey) * APAD + voff) * 2;
        const uint32_t vb1 = sbVh + (uint32_t)((j0 + 16 + vkey) * APAD + voff) * 2;
        #pragma unroll
        for (int nc = 0; nc < 4; nc++) {
            uint32_t v0[4], v1[4];
            ldsm_x4t(vb0 + nc * 32, v0);
            ldsm_x4t(vb1 + nc * 32, v1);
            #pragma unroll
            for (int mt = 0; mt < 2; mt++) {
                mma_fp16(O[mt][nc * 2],     pa0[mt], v0[0], v0[1]);
                mma_fp16(O[mt][nc * 2 + 1], pa0[mt], v0[2], v0[3]);
                mma_fp16(O[mt][nc * 2],     pa1[mt], v1[0], v1[1]);
                mma_fp16(O[mt][nc * 2 + 1], pa1[mt], v1[2], v1[3]);
            }
        }
    }

    // ---- epilogue: quad-reduce l, normalize, store ----
    float inv[4];
    #pragma unroll
    for (int rg = 0; rg < 4; rg++) {
        float ls = lsum[rg];
        ls += __shfl_xor_sync(0xFFFFFFFFu, ls, 1);
        ls += __shfl_xor_sync(0xFFFFFFFFu, ls, 2);
        inv[rg] = 1.f / ls;
    }
    float* ob = out + ((size_t)b * TT) * DKV;
    #pragma unroll
    for (int mt = 0; mt < 2; mt++) {
        #pragma unroll
        for (int h = 0; h < 2; h++) {
            const int row = Q0 + mt * 16 + g + h * 8;
            const float iv = inv[mt * 2 + h];
            #pragma unroll
            for (int n = 0; n < 8; n++) {
                *(float2*)(ob + (size_t)row * DKV + n * 8 + tg * 2) =
                    make_float2(O[mt][n][h * 2] * iv, O[mt][n][h * 2 + 1] * iv);
            }
        }
    }
}

// ---------------------------------------------------------------------------
// kernel_launch — graph-capturable, allocation-free
// ---------------------------------------------------------------------------
extern "C" void kernel_launch(void* const* d_in, const int* in_sizes, int n_in,
                              void* d_out, int out_size) {
    const float* x  = (const float*)d_in[0];
    const float* Wq = (const float*)d_in[1];
    const float* Wk = (const float*)d_in[2];
    const float* Wv = (const float*)d_in[3];
    float* out = (float*)d_out;
    (void)in_sizes; (void)n_in; (void)out_size;

    wconv_kernel<<<36, 256>>>(Wq, Wk, Wv);

    const int proj_smem = SM_ELEMS * (int)sizeof(__half);        // 76.8 KB
    cudaFuncSetAttribute(proj_mma_kernel,
                         cudaFuncAttributeMaxDynamicSharedMemorySize, proj_smem);
    proj_mma_kernel<<<BT / BM, 256, proj_smem>>>(x);

    const int attn_smem = 2 * KV_SZ * (int)sizeof(__half);       // 72 KB
    cudaFuncSetAttribute(attn_mma_kernel,
                         cudaFuncAttributeMaxDynamicSharedMemorySize, attn_smem);
    attn_mma_kernel<<<BATCH, 256, attn_smem>>>(out);
}